// round 10
// baseline (speedup 1.0000x reference)
#include <cuda_runtime.h>
#include <cuda_fp16.h>
#include <cstdint>

#define DIM     384
#define NHEAD   12
#define NTOK    49
#define BWIN    4096
#define MROWS   (BWIN * NTOK)      // 200704
#define KDIM    384
#define N1      (3 * DIM)          // 1152

// ---------------- static device scratch ----------------
__device__ __half g_q[(size_t)MROWS * DIM];
__device__ __half g_k[(size_t)MROWS * DIM];
__device__ __half g_v[(size_t)MROWS * DIM];
__device__ __half g_xh[(size_t)MROWS * DIM];
__device__ __half g_atth[(size_t)MROWS * DIM];
__device__ __half g_w1h[(size_t)N1 * KDIM];
__device__ __half g_w2h[(size_t)DIM * KDIM];
__device__ float  g_comb[(size_t)NHEAD * 64 * 64 * 64];   // bias+mask, padded

// ---------------- helpers ----------------
__device__ __forceinline__ uint32_t s2u(const void* p) {
    uint32_t a;
    asm("{ .reg .u64 t; cvta.to.shared.u64 t, %1; cvt.u32.u64 %0, t; }" : "=r"(a) : "l"(p));
    return a;
}
__device__ __forceinline__ void cpasync16(uint32_t dst, const void* src) {
    asm volatile("cp.async.cg.shared.global [%0], [%1], 16;" :: "r"(dst), "l"(src));
}
__device__ __forceinline__ void cp_commit() { asm volatile("cp.async.commit_group;" ::: "memory"); }
__device__ __forceinline__ void cp_wait1()  { asm volatile("cp.async.wait_group 1;" ::: "memory"); }
__device__ __forceinline__ void cp_wait0()  { asm volatile("cp.async.wait_group 0;" ::: "memory"); }
__device__ __forceinline__ void mma_f16(float* c, const uint32_t* a, const uint32_t* b) {
    asm volatile(
        "mma.sync.aligned.m16n8k16.row.col.f32.f16.f16.f32 "
        "{%0,%1,%2,%3}, {%4,%5,%6,%7}, {%8,%9}, {%0,%1,%2,%3};"
        : "+f"(c[0]), "+f"(c[1]), "+f"(c[2]), "+f"(c[3])
        : "r"(a[0]), "r"(a[1]), "r"(a[2]), "r"(a[3]), "r"(b[0]), "r"(b[1]));
}

// ---------------------------------------------------------------------------
__global__ void half_pass(const float* __restrict__ in, __half* __restrict__ outp, size_t n4)
{
    for (size_t i = blockIdx.x * blockDim.x + threadIdx.x; i < n4;
         i += (size_t)gridDim.x * blockDim.x) {
        float4 v = ((const float4*)in)[i];
        __half2 h0 = __floats2half2_rn(v.x, v.y);
        __half2 h1 = __floats2half2_rn(v.z, v.w);
        uint2 pk = { *(uint32_t*)&h0, *(uint32_t*)&h1 };
        ((uint2*)outp)[i] = pk;
    }
}

// ---------------------------------------------------------------------------
// comb[h][wm][i][j] = bias[h,i,j] + mask[wm,i,j]  (i,j < 49), else -1e30
// ---------------------------------------------------------------------------
__global__ void comb_pre(const float* __restrict__ bt, const int* __restrict__ rel,
                         const float* __restrict__ mask, float* __restrict__ comb)
{
    const int total = NHEAD * 64 * 64 * 64;
    for (int t = blockIdx.x * blockDim.x + threadIdx.x; t < total;
         t += gridDim.x * blockDim.x) {
        int j = t & 63, i = (t >> 6) & 63, wm = (t >> 12) & 63, h = t >> 18;
        float val = -1e30f;
        if (i < NTOK && j < NTOK) {
            int e = i * NTOK + j;
            val = bt[rel[e] * NHEAD + h] + mask[(size_t)wm * 2401 + e];
        }
        comb[t] = val;
    }
}

// ---------------------------------------------------------------------------
// FP16 HMMA GEMM (proven): C = A * B^T + bias. Block 128x128, BK=64, 8 warps.
// mode 0: scatter into q (scaled) / k / v head-major FP16
// mode 1: row-major fp32 out + bias
// ---------------------------------------------------------------------------
#define PADH 72
#define HBUFF (128 * PADH)
#define SMEMH (4 * HBUFF * 2)

__global__ __launch_bounds__(256, 2)
void gemm_f16(const __half* __restrict__ A, const __half* __restrict__ Bm,
              const float* __restrict__ bias, float* __restrict__ outp,
              __half* __restrict__ qo, __half* __restrict__ ko, __half* __restrict__ vo,
              int mode)
{
    extern __shared__ __align__(16) __half smh[];
    const int tid = threadIdx.x;
    const int wid = tid >> 5, lane = tid & 31;
    const int wm = wid & 1, wn = wid >> 1;
    const int bn = blockIdx.x, bm = blockIdx.y;
    const uint32_t smb = s2u(smh);

    const int lrow = tid >> 1;
    const int lcol0 = (tid & 1) * 32;

    auto issue = [&](int ch) {
        const int st = ch & 1;
        const uint32_t da = smb + (uint32_t)(st * 2 * HBUFF) * 2;
        const uint32_t db = da + HBUFF * 2;
        const int kk = ch * 64;
        const __half* ga = A  + (size_t)(bm * 128) * KDIM + kk;
        const __half* gb = Bm + (size_t)(bn * 128) * KDIM + kk;
#pragma unroll
        for (int p = 0; p < 4; p++) {
            int c = lcol0 + p * 8;
            cpasync16(da + (lrow * PADH + c) * 2, ga + (size_t)lrow * KDIM + c);
            cpasync16(db + (lrow * PADH + c) * 2, gb + (size_t)lrow * KDIM + c);
        }
        cp_commit();
    };

    float cacc[4][4][4];
#pragma unroll
    for (int i = 0; i < 4; i++)
#pragma unroll
        for (int j = 0; j < 4; j++)
#pragma unroll
            for (int q = 0; q < 4; q++) cacc[i][j][q] = 0.f;

    issue(0);
    const int r4 = lane >> 2, c4 = lane & 3;

    for (int ch = 0; ch < 6; ch++) {
        if (ch + 1 < 6) issue(ch + 1);
        if (ch == 5) cp_wait0(); else cp_wait1();
        __syncthreads();

        const __half* As = smh + (ch & 1) * 2 * HBUFF;
        const __half* Bs = As + HBUFF;
#pragma unroll
        for (int k16 = 0; k16 < 4; k16++) {
            uint32_t af[4][4], bf[4][2];
#pragma unroll
            for (int mi = 0; mi < 4; mi++) {
                const __half* ap = As + (wm * 64 + mi * 16 + r4) * PADH + k16 * 16 + 2 * c4;
                af[mi][0] = *(const uint32_t*)ap;
                af[mi][1] = *(const uint32_t*)(ap + 8 * PADH);
                af[mi][2] = *(const uint32_t*)(ap + 8);
                af[mi][3] = *(const uint32_t*)(ap + 8 * PADH + 8);
            }
#pragma unroll
            for (int ni = 0; ni < 4; ni++) {
                const __half* bp = Bs + (wn * 32 + ni * 8 + r4) * PADH + k16 * 16 + 2 * c4;
                bf[ni][0] = *(const uint32_t*)bp;
                bf[ni][1] = *(const uint32_t*)(bp + 8);
            }
#pragma unroll
            for (int mi = 0; mi < 4; mi++)
#pragma unroll
                for (int ni = 0; ni < 4; ni++)
                    mma_f16(cacc[mi][ni], af[mi], bf[ni]);
        }
        __syncthreads();
    }

    const float qscale = 0.17677669529663687f;
#pragma unroll
    for (int mi = 0; mi < 4; mi++) {
#pragma unroll
        for (int ni = 0; ni < 4; ni++) {
            const int m0 = bm * 128 + wm * 64 + mi * 16 + (lane >> 2);
            const int n0 = bn * 128 + wn * 32 + ni * 8 + 2 * (lane & 3);
            const float b0 = __ldg(bias + n0), b1 = __ldg(bias + n0 + 1);
            float2 v0 = { cacc[mi][ni][0] + b0, cacc[mi][ni][1] + b1 };
            float2 v1 = { cacc[mi][ni][2] + b0, cacc[mi][ni][3] + b1 };
            if (mode == 0) {
                const int arr = n0 / DIM, nin = n0 - arr * DIM;
                const int h = nin >> 5, d = nin & 31;
                if (arr == 0) { v0.x *= qscale; v0.y *= qscale; v1.x *= qscale; v1.y *= qscale; }
                __half* basep = (arr == 0 ? qo : (arr == 1 ? ko : vo));
                int w0 = m0 / NTOK, i0 = m0 - w0 * NTOK;
                *(__half2*)(basep + (((size_t)(w0 * NHEAD + h) * NTOK + i0) << 5) + d) =
                    __floats2half2_rn(v0.x, v0.y);
                int m1 = m0 + 8;
                int w1 = m1 / NTOK, i1 = m1 - w1 * NTOK;
                *(__half2*)(basep + (((size_t)(w1 * NHEAD + h) * NTOK + i1) << 5) + d) =
                    __floats2half2_rn(v1.x, v1.y);
            } else {
                *(float2*)(outp + (size_t)m0 * DIM + n0) = v0;
                *(float2*)(outp + (size_t)(m0 + 8) * DIM + n0) = v1;
            }
        }
    }
}

// ---------------------------------------------------------------------------
// FP16 MMA attention: block per (h,w), 4 warps, register softmax,
// P aliased over qs/ks. All MMA operands fp16, accum fp32.
// ---------------------------------------------------------------------------
#define QPH 40    // halves per q/k row
#define SPH 72    // halves per P row
#define VPH 72    // halves per vt row

__global__ __launch_bounds__(128, 8)
void attn_mma(const __half* __restrict__ qg, const __half* __restrict__ kg,
              const __half* __restrict__ vg, const float* __restrict__ comb,
              __half* __restrict__ out)
{
    const int h = blockIdx.x, w = blockIdx.y, tid = threadIdx.x;
    const int wid = tid >> 5, lane = tid & 31;
    const int r4 = lane >> 2, c4 = lane & 3;

    __shared__ __align__(16) union SU {
        struct { __half qs[64][QPH]; __half ks[64][QPH]; } a;   // 10240 B
        __half ps[64][SPH];                                     // 9216 B
    } u;
    __shared__ __align__(16) __half vt[32][VPH];                // 4608 B

    __half (*qs)[QPH] = u.a.qs;
    __half (*ks)[QPH] = u.a.ks;

    // zero pads: q/k rows 49..63 (cols 0..31 used), vt cols 49..63
    for (int t = tid; t < 15 * 32; t += 128) {
        int r = t >> 5, c = t & 31;
        qs[49 + r][c] = __ushort_as_half(0);
        ks[49 + r][c] = __ushort_as_half(0);
    }
    for (int t = tid; t < 32 * 15; t += 128) {
        int d = t / 15, j = t - d * 15;
        vt[d][49 + j] = __ushort_as_half(0);
    }

    const size_t base = ((size_t)(w * NHEAD + h) * NTOK) << 5;
    for (int t = tid; t < 49 * 16; t += 128) {
        int i = t >> 4, d2 = t & 15;
        __half2 qv = *(const __half2*)(qg + base + (i << 5) + 2 * d2);
        __half2 kv = *(const __half2*)(kg + base + (i << 5) + 2 * d2);
        __half2 vv = *(const __half2*)(vg + base + (i << 5) + 2 * d2);
        *(__half2*)&qs[i][2 * d2] = qv;
        *(__half2*)&ks[i][2 * d2] = kv;
        vt[2 * d2][i]     = __low2half(vv);
        vt[2 * d2 + 1][i] = __high2half(vv);
    }
    __syncthreads();

    const int m0 = wid * 16;

    // ---- S = Q K^T (fp16 MMA, K=32 -> 2 k16 steps) ----
    float sacc[8][4];
#pragma unroll
    for (int ni = 0; ni < 8; ni++)
#pragma unroll
        for (int q = 0; q < 4; q++) sacc[ni][q] = 0.f;

#pragma unroll
    for (int k16 = 0; k16 < 2; k16++) {
        uint32_t af[4];
        const __half* ap = &qs[m0 + r4][k16 * 16 + 2 * c4];
        af[0] = *(const uint32_t*)ap;
        af[1] = *(const uint32_t*)(ap + 8 * QPH);
        af[2] = *(const uint32_t*)(ap + 8);
        af[3] = *(const uint32_t*)(ap + 8 * QPH + 8);
#pragma unroll
        for (int ni = 0; ni < 8; ni++) {
            uint32_t bf[2];
            const __half* bp = &ks[ni * 8 + r4][k16 * 16 + 2 * c4];
            bf[0] = *(const uint32_t*)bp;
            bf[1] = *(const uint32_t*)(bp + 8);
            mma_f16(sacc[ni], af, bf);
        }
    }

    // ---- add comb (bias+mask) ----
    const float* cb = comb + (((size_t)h * 64 + (w & 63)) << 12);
    const int i0 = m0 + r4, i1 = i0 + 8;
#pragma unroll
    for (int ni = 0; ni < 8; ni++) {
        const int j0 = ni * 8 + 2 * c4;
        float2 c0 = *(const float2*)(cb + i0 * 64 + j0);
        float2 c1 = *(const float2*)(cb + i1 * 64 + j0);
        sacc[ni][0] += c0.x;
        sacc[ni][1] += c0.y;
        sacc[ni][2] += c1.x;
        sacc[ni][3] += c1.y;
    }

    // ---- register softmax (4-lane groups per row) ----
    float mx0 = -1e30f, mx1 = -1e30f;
#pragma unroll
    for (int ni = 0; ni < 8; ni++) {
        mx0 = fmaxf(mx0, fmaxf(sacc[ni][0], sacc[ni][1]));
        mx1 = fmaxf(mx1, fmaxf(sacc[ni][2], sacc[ni][3]));
    }
#pragma unroll
    for (int o = 1; o <= 2; o <<= 1) {
        mx0 = fmaxf(mx0, __shfl_xor_sync(~0u, mx0, o));
        mx1 = fmaxf(mx1, __shfl_xor_sync(~0u, mx1, o));
    }
    float sum0 = 0.f, sum1 = 0.f;
#pragma unroll
    for (int ni = 0; ni < 8; ni++) {
        sacc[ni][0] = __expf(sacc[ni][0] - mx0); sum0 += sacc[ni][0];
        sacc[ni][1] = __expf(sacc[ni][1] - mx0); sum0 += sacc[ni][1];
        sacc[ni][2] = __expf(sacc[ni][2] - mx1); sum1 += sacc[ni][2];
        sacc[ni][3] = __expf(sacc[ni][3] - mx1); sum1 += sacc[ni][3];
    }
#pragma unroll
    for (int o = 1; o <= 2; o <<= 1) {
        sum0 += __shfl_xor_sync(~0u, sum0, o);
        sum1 += __shfl_xor_sync(~0u, sum1, o);
    }
    const float inv0 = 1.0f / sum0, inv1 = 1.0f / sum1;

    __syncthreads();   // all qs/ks reads done before ps overwrite

    // ---- write P (fp16) into aliased ps ----
#pragma unroll
    for (int ni = 0; ni < 8; ni++) {
        const int j0 = ni * 8 + 2 * c4;
        *(__half2*)&u.ps[i0][j0] = __floats2half2_rn(sacc[ni][0] * inv0, sacc[ni][1] * inv0);
        *(__half2*)&u.ps[i1][j0] = __floats2half2_rn(sacc[ni][2] * inv1, sacc[ni][3] * inv1);
    }
    __syncthreads();

    // ---- O = P V (fp16 MMA, K=64 -> 4 k16 steps) ----
    float oacc[4][4];
#pragma unroll
    for (int ni = 0; ni < 4; ni++)
#pragma unroll
        for (int q = 0; q < 4; q++) oacc[ni][q] = 0.f;

#pragma unroll
    for (int k16 = 0; k16 < 4; k16++) {
        uint32_t af[4];
        const __half* ap = &u.ps[m0 + r4][k16 * 16 + 2 * c4];
        af[0] = *(const uint32_t*)ap;
        af[1] = *(const uint32_t*)(ap + 8 * SPH);
        af[2] = *(const uint32_t*)(ap + 8);
        af[3] = *(const uint32_t*)(ap + 8 * SPH + 8);
#pragma unroll
        for (int ni = 0; ni < 4; ni++) {
            uint32_t bf[2];
            const __half* bp = &vt[ni * 8 + r4][k16 * 16 + 2 * c4];
            bf[0] = *(const uint32_t*)bp;
            bf[1] = *(const uint32_t*)(bp + 8);
            mma_f16(oacc[ni], af, bf);
        }
    }

#pragma unroll
    for (int ni = 0; ni < 4; ni++) {
        const int d0 = ni * 8 + 2 * c4;
        if (i0 < 49) {
            *(__half2*)(out + ((size_t)w * 49 + i0) * DIM + h * 32 + d0) =
                __floats2half2_rn(oacc[ni][0], oacc[ni][1]);
        }
        if (i1 < 49) {
            *(__half2*)(out + ((size_t)w * 49 + i1) * DIM + h * 32 + d0) =
                __floats2half2_rn(oacc[ni][2], oacc[ni][3]);
        }
    }
}

// ---------------------------------------------------------------------------
extern "C" void kernel_launch(void* const* d_in, const int* in_sizes, int n_in,
                              void* d_out, int out_size)
{
    const float* x      = (const float*)d_in[0];
    const float* mask   = (const float*)d_in[1];
    const float* qkv_w  = (const float*)d_in[2];
    const float* qkv_b  = (const float*)d_in[3];
    const float* proj_w = (const float*)d_in[4];
    const float* proj_b = (const float*)d_in[5];
    const float* bt     = (const float*)d_in[6];
    const int*   rel    = (const int*)d_in[7];
    float* out = (float*)d_out;

    float *combp;
    __half *qp, *kp, *vp, *xh, *atth, *w1h, *w2h;
    cudaGetSymbolAddress((void**)&qp, g_q);
    cudaGetSymbolAddress((void**)&kp, g_k);
    cudaGetSymbolAddress((void**)&vp, g_v);
    cudaGetSymbolAddress((void**)&combp, g_comb);
    cudaGetSymbolAddress((void**)&xh, g_xh);
    cudaGetSymbolAddress((void**)&atth, g_atth);
    cudaGetSymbolAddress((void**)&w1h, g_w1h);
    cudaGetSymbolAddress((void**)&w2h, g_w2h);

    cudaFuncSetAttribute(gemm_f16, cudaFuncAttributeMaxDynamicSharedMemorySize, SMEMH);

    half_pass<<<1184, 256>>>(x, xh, (size_t)MROWS * DIM / 4);
    half_pass<<<112, 256>>>(qkv_w, w1h, (size_t)N1 * KDIM / 4);
    half_pass<<<48, 256>>>(proj_w, w2h, (size_t)DIM * KDIM / 4);
    comb_pre<<<1536, 256>>>(bt, rel, mask, combp);

    dim3 g1(N1 / 128, MROWS / 128);    // 9 x 1568
    gemm_f16<<<g1, 256, SMEMH>>>(xh, w1h, qkv_b, nullptr, qp, kp, vp, 0);

    dim3 ga(NHEAD, BWIN);              // 12 x 4096
    attn_mma<<<ga, 128>>>(qp, kp, vp, combp, atth);

    dim3 g2(DIM / 128, MROWS / 128);   // 3 x 1568
    gemm_f16<<<g2, 256, SMEMH>>>(atth, w2h, proj_b, out, nullptr, nullptr, nullptr, 1);
}

// round 11
// speedup vs baseline: 1.3471x; 1.3471x over previous
#include <cuda_runtime.h>
#include <cuda_fp16.h>
#include <cstdint>

#define DIM     384
#define NHEAD   12
#define NTOK    49
#define BWIN    4096
#define MROWS   (BWIN * NTOK)      // 200704
#define KDIM    384
#define N1      (3 * DIM)          // 1152

// ---------------- static device scratch ----------------
__device__ float  g_q[(size_t)MROWS * DIM];
__device__ float  g_k[(size_t)MROWS * DIM];
__device__ float  g_v[(size_t)MROWS * DIM];
__device__ __half g_xh[(size_t)MROWS * DIM];
__device__ __half g_atth[(size_t)MROWS * DIM];
__device__ __half g_w1h[(size_t)N1 * KDIM];
__device__ __half g_w2h[(size_t)DIM * KDIM];
__device__ float  g_comb[(size_t)NHEAD * 64 * 64 * 64];   // bias+mask, padded

// ---------------- helpers ----------------
__device__ __forceinline__ uint32_t s2u(const void* p) {
    uint32_t a;
    asm("{ .reg .u64 t; cvta.to.shared.u64 t, %1; cvt.u32.u64 %0, t; }" : "=r"(a) : "l"(p));
    return a;
}
__device__ __forceinline__ void cpasync16(uint32_t dst, const void* src) {
    asm volatile("cp.async.cg.shared.global [%0], [%1], 16;" :: "r"(dst), "l"(src));
}
__device__ __forceinline__ void cp_commit() { asm volatile("cp.async.commit_group;" ::: "memory"); }
__device__ __forceinline__ void cp_wait1()  { asm volatile("cp.async.wait_group 1;" ::: "memory"); }
__device__ __forceinline__ void cp_wait0()  { asm volatile("cp.async.wait_group 0;" ::: "memory"); }
__device__ __forceinline__ uint32_t f2tf32(float f) {
    uint32_t u;
    asm("cvt.rna.tf32.f32 %0, %1;" : "=r"(u) : "f"(f));
    return u;
}
__device__ __forceinline__ float rnd_tf32(float f) {
    return __uint_as_float(f2tf32(f));
}
__device__ __forceinline__ void mma_tf32(float* c, const uint32_t* a, const uint32_t* b) {
    asm volatile(
        "mma.sync.aligned.m16n8k8.row.col.f32.tf32.tf32.f32 "
        "{%0,%1,%2,%3}, {%4,%5,%6,%7}, {%8,%9}, {%0,%1,%2,%3};"
        : "+f"(c[0]), "+f"(c[1]), "+f"(c[2]), "+f"(c[3])
        : "r"(a[0]), "r"(a[1]), "r"(a[2]), "r"(a[3]), "r"(b[0]), "r"(b[1]));
}
__device__ __forceinline__ void mma_f16(float* c, const uint32_t* a, const uint32_t* b) {
    asm volatile(
        "mma.sync.aligned.m16n8k16.row.col.f32.f16.f16.f32 "
        "{%0,%1,%2,%3}, {%4,%5,%6,%7}, {%8,%9}, {%0,%1,%2,%3};"
        : "+f"(c[0]), "+f"(c[1]), "+f"(c[2]), "+f"(c[3])
        : "r"(a[0]), "r"(a[1]), "r"(a[2]), "r"(a[3]), "r"(b[0]), "r"(b[1]));
}
__device__ __forceinline__ void ldsm_x4(uint32_t& r0, uint32_t& r1, uint32_t& r2, uint32_t& r3,
                                        uint32_t addr) {
    asm volatile("ldmatrix.sync.aligned.m8n8.x4.shared.b16 {%0,%1,%2,%3}, [%4];"
                 : "=r"(r0), "=r"(r1), "=r"(r2), "=r"(r3) : "r"(addr));
}

// ---------------------------------------------------------------------------
__global__ void half_pass(const float* __restrict__ in, __half* __restrict__ outp, size_t n4)
{
    for (size_t i = blockIdx.x * blockDim.x + threadIdx.x; i < n4;
         i += (size_t)gridDim.x * blockDim.x) {
        float4 v = ((const float4*)in)[i];
        __half2 h0 = __floats2half2_rn(v.x, v.y);
        __half2 h1 = __floats2half2_rn(v.z, v.w);
        uint2 pk = { *(uint32_t*)&h0, *(uint32_t*)&h1 };
        ((uint2*)outp)[i] = pk;
    }
}

// ---------------------------------------------------------------------------
// comb[h][wm][i][j] = bias[h,i,j] + mask[wm,i,j]  (i,j < 49), else -1e30
// ---------------------------------------------------------------------------
__global__ void comb_pre(const float* __restrict__ bt, const int* __restrict__ rel,
                         const float* __restrict__ mask, float* __restrict__ comb)
{
    const int total = NHEAD * 64 * 64 * 64;
    for (int t = blockIdx.x * blockDim.x + threadIdx.x; t < total;
         t += gridDim.x * blockDim.x) {
        int j = t & 63, i = (t >> 6) & 63, wm = (t >> 12) & 63, h = t >> 18;
        float val = -1e30f;
        if (i < NTOK && j < NTOK) {
            int e = i * NTOK + j;
            val = bt[rel[e] * NHEAD + h] + mask[(size_t)wm * 2401 + e];
        }
        comb[t] = val;
    }
}

// ---------------------------------------------------------------------------
// FP16 HMMA GEMM with ldmatrix fragments: C = A * B^T + bias.
// Block 128x128, BK=64, 8 warps (2m x 4n), warp tile 64x32, m16n8k16.
// mode 0: scatter into q (scaled, tf32-rounded) / k / v head-major fp32
// mode 1: row-major fp32 out + bias
// ---------------------------------------------------------------------------
#define PADH 72
#define HBUFF (128 * PADH)
#define SMEMH (4 * HBUFF * 2)

__global__ __launch_bounds__(256, 2)
void gemm_f16(const __half* __restrict__ A, const __half* __restrict__ Bm,
              const float* __restrict__ bias, float* __restrict__ outp,
              float* __restrict__ qo, float* __restrict__ ko, float* __restrict__ vo,
              int mode)
{
    extern __shared__ __align__(16) __half smh[];
    const int tid = threadIdx.x;
    const int wid = tid >> 5, lane = tid & 31;
    const int wm = wid & 1, wn = wid >> 1;
    const int bn = blockIdx.x, bm = blockIdx.y;
    const uint32_t smb = s2u(smh);

    const int lrow = tid >> 1;
    const int lcol0 = (tid & 1) * 32;

    auto issue = [&](int ch) {
        const int st = ch & 1;
        const uint32_t da = smb + (uint32_t)(st * 2 * HBUFF) * 2;
        const uint32_t db = da + HBUFF * 2;
        const int kk = ch * 64;
        const __half* ga = A  + (size_t)(bm * 128) * KDIM + kk;
        const __half* gb = Bm + (size_t)(bn * 128) * KDIM + kk;
#pragma unroll
        for (int p = 0; p < 4; p++) {
            int c = lcol0 + p * 8;
            cpasync16(da + (lrow * PADH + c) * 2, ga + (size_t)lrow * KDIM + c);
            cpasync16(db + (lrow * PADH + c) * 2, gb + (size_t)lrow * KDIM + c);
        }
        cp_commit();
    };

    float cacc[4][4][4];
#pragma unroll
    for (int i = 0; i < 4; i++)
#pragma unroll
        for (int j = 0; j < 4; j++)
#pragma unroll
            for (int q = 0; q < 4; q++) cacc[i][j][q] = 0.f;

    issue(0);

    // ldmatrix lane-address offsets (halves)
    const int a_row = wm * 64 + ((lane >> 3) & 1) * 8 + (lane & 7);
    const int a_col = (lane >> 4) * 8;
    const uint32_t a_off = (uint32_t)(a_row * PADH + a_col) * 2;
    const int b_row = wn * 32 + ((lane >> 4) & 1) * 8 + (lane & 7);
    const int b_col = ((lane >> 3) & 1) * 8;
    const uint32_t b_off = (uint32_t)(b_row * PADH + b_col) * 2;

    for (int ch = 0; ch < 6; ch++) {
        if (ch + 1 < 6) issue(ch + 1);
        if (ch == 5) cp_wait0(); else cp_wait1();
        __syncthreads();

        const uint32_t Asa = smb + (uint32_t)((ch & 1) * 2 * HBUFF) * 2;
        const uint32_t Bsa = Asa + HBUFF * 2;
#pragma unroll
        for (int k16 = 0; k16 < 4; k16++) {
            uint32_t af[4][4], bf[4][2];
            const uint32_t ak = Asa + a_off + k16 * 32;
            const uint32_t bk = Bsa + b_off + k16 * 32;
#pragma unroll
            for (int mi = 0; mi < 4; mi++)
                ldsm_x4(af[mi][0], af[mi][1], af[mi][2], af[mi][3],
                        ak + (uint32_t)(mi * 16 * PADH) * 2);
#pragma unroll
            for (int np = 0; np < 2; np++)
                ldsm_x4(bf[2 * np][0], bf[2 * np][1], bf[2 * np + 1][0], bf[2 * np + 1][1],
                        bk + (uint32_t)(np * 16 * PADH) * 2);
#pragma unroll
            for (int mi = 0; mi < 4; mi++)
#pragma unroll
                for (int ni = 0; ni < 4; ni++)
                    mma_f16(cacc[mi][ni], af[mi], bf[ni]);
        }
        __syncthreads();
    }

    const float qscale = 0.17677669529663687f;
#pragma unroll
    for (int mi = 0; mi < 4; mi++) {
#pragma unroll
        for (int ni = 0; ni < 4; ni++) {
            const int m0 = bm * 128 + wm * 64 + mi * 16 + (lane >> 2);
            const int n0 = bn * 128 + wn * 32 + ni * 8 + 2 * (lane & 3);
            const float b0 = __ldg(bias + n0), b1 = __ldg(bias + n0 + 1);
            float2 v0 = { cacc[mi][ni][0] + b0, cacc[mi][ni][1] + b1 };
            float2 v1 = { cacc[mi][ni][2] + b0, cacc[mi][ni][3] + b1 };
            if (mode == 0) {
                const int arr = n0 / DIM, nin = n0 - arr * DIM;
                const int h = nin >> 5, d = nin & 31;
                if (arr == 0) { v0.x *= qscale; v0.y *= qscale; v1.x *= qscale; v1.y *= qscale; }
                v0.x = rnd_tf32(v0.x); v0.y = rnd_tf32(v0.y);
                v1.x = rnd_tf32(v1.x); v1.y = rnd_tf32(v1.y);
                float* basep = (arr == 0 ? qo : (arr == 1 ? ko : vo));
                int w0 = m0 / NTOK, i0 = m0 - w0 * NTOK;
                *(float2*)(basep + (((size_t)(w0 * NHEAD + h) * NTOK + i0) << 5) + d) = v0;
                int m1 = m0 + 8;
                int w1 = m1 / NTOK, i1 = m1 - w1 * NTOK;
                *(float2*)(basep + (((size_t)(w1 * NHEAD + h) * NTOK + i1) << 5) + d) = v1;
            } else {
                *(float2*)(outp + (size_t)m0 * DIM + n0) = v0;
                *(float2*)(outp + (size_t)(m0 + 8) * DIM + n0) = v1;
            }
        }
    }
}

// ---------------------------------------------------------------------------
// MMA attention (tf32, proven R9): register softmax, smem aliasing.
// Output written as fp16 (gemm2's A operand).
// ---------------------------------------------------------------------------
#define QP 36
#define SP 69
#define VP 68

__global__ __launch_bounds__(128, 8)
void attn_mma(const float* __restrict__ qg, const float* __restrict__ kg,
              const float* __restrict__ vg, const float* __restrict__ comb,
              __half* __restrict__ out)
{
    const int h = blockIdx.x, w = blockIdx.y, tid = threadIdx.x;
    const int wid = tid >> 5, lane = tid & 31;
    const int r4 = lane >> 2, c4 = lane & 3;

    __shared__ __align__(16) union SU {
        struct { float qs[64][QP]; float ks[64][QP]; } a;
        float ss[64][SP];
    } u;
    __shared__ __align__(16) float vt[32][VP];

    float (*qs)[QP] = u.a.qs;
    float (*ks)[QP] = u.a.ks;

    for (int t = tid; t < 15 * QP; t += 128) {
        int r = t / QP, c = t - r * QP;
        qs[49 + r][c] = 0.f;
        ks[49 + r][c] = 0.f;
    }
    for (int t = tid; t < 32 * 15; t += 128) {
        int d = t / 15, j = t - d * 15;
        vt[d][49 + j] = 0.f;
    }

    const size_t base = ((size_t)(w * NHEAD + h) * NTOK) << 5;
    for (int t = tid; t < 49 * 32; t += 128) {
        int i = t >> 5, d = t & 31;
        qs[i][d] = qg[base + t];
        ks[i][d] = kg[base + t];
        vt[d][i] = vg[base + t];
    }
    __syncthreads();

    const int m0 = wid * 16;

    float sacc[8][4];
#pragma unroll
    for (int ni = 0; ni < 8; ni++)
#pragma unroll
        for (int q = 0; q < 4; q++) sacc[ni][q] = 0.f;

#pragma unroll
    for (int k8 = 0; k8 < 4; k8++) {
        uint32_t af[4];
        const uint32_t* ap = (const uint32_t*)&qs[m0 + r4][k8 * 8 + c4];
        af[0] = ap[0];
        af[1] = ap[8 * QP];
        af[2] = ap[4];
        af[3] = ap[8 * QP + 4];
#pragma unroll
        for (int ni = 0; ni < 8; ni++) {
            uint32_t bf[2];
            const uint32_t* bp = (const uint32_t*)&ks[ni * 8 + r4][k8 * 8 + c4];
            bf[0] = bp[0];
            bf[1] = bp[4];
            mma_tf32(sacc[ni], af, bf);
        }
    }

    const float* cb = comb + (((size_t)h * 64 + (w & 63)) << 12);
    const int i0 = m0 + r4, i1 = i0 + 8;
#pragma unroll
    for (int ni = 0; ni < 8; ni++) {
        const int j0 = ni * 8 + 2 * c4;
        float2 c0 = *(const float2*)(cb + i0 * 64 + j0);
        float2 c1 = *(const float2*)(cb + i1 * 64 + j0);
        sacc[ni][0] += c0.x;
        sacc[ni][1] += c0.y;
        sacc[ni][2] += c1.x;
        sacc[ni][3] += c1.y;
    }

    float mx0 = -1e30f, mx1 = -1e30f;
#pragma unroll
    for (int ni = 0; ni < 8; ni++) {
        mx0 = fmaxf(mx0, fmaxf(sacc[ni][0], sacc[ni][1]));
        mx1 = fmaxf(mx1, fmaxf(sacc[ni][2], sacc[ni][3]));
    }
#pragma unroll
    for (int o = 1; o <= 2; o <<= 1) {
        mx0 = fmaxf(mx0, __shfl_xor_sync(~0u, mx0, o));
        mx1 = fmaxf(mx1, __shfl_xor_sync(~0u, mx1, o));
    }
    float sum0 = 0.f, sum1 = 0.f;
#pragma unroll
    for (int ni = 0; ni < 8; ni++) {
        sacc[ni][0] = __expf(sacc[ni][0] - mx0); sum0 += sacc[ni][0];
        sacc[ni][1] = __expf(sacc[ni][1] - mx0); sum0 += sacc[ni][1];
        sacc[ni][2] = __expf(sacc[ni][2] - mx1); sum1 += sacc[ni][2];
        sacc[ni][3] = __expf(sacc[ni][3] - mx1); sum1 += sacc[ni][3];
    }
#pragma unroll
    for (int o = 1; o <= 2; o <<= 1) {
        sum0 += __shfl_xor_sync(~0u, sum0, o);
        sum1 += __shfl_xor_sync(~0u, sum1, o);
    }
    const float inv0 = 1.0f / sum0, inv1 = 1.0f / sum1;

    __syncthreads();

#pragma unroll
    for (int ni = 0; ni < 8; ni++) {
        const int j0 = ni * 8 + 2 * c4;
        u.ss[i0][j0]     = rnd_tf32(sacc[ni][0] * inv0);
        u.ss[i0][j0 + 1] = rnd_tf32(sacc[ni][1] * inv0);
        u.ss[i1][j0]     = rnd_tf32(sacc[ni][2] * inv1);
        u.ss[i1][j0 + 1] = rnd_tf32(sacc[ni][3] * inv1);
    }
    __syncthreads();

    float oacc[4][4];
#pragma unroll
    for (int ni = 0; ni < 4; ni++)
#pragma unroll
        for (int q = 0; q < 4; q++) oacc[ni][q] = 0.f;

#pragma unroll
    for (int k8 = 0; k8 < 8; k8++) {
        uint32_t af[4];
        const uint32_t* ap = (const uint32_t*)&u.ss[m0 + r4][k8 * 8 + c4];
        af[0] = ap[0];
        af[1] = ap[8 * SP];
        af[2] = ap[4];
        af[3] = ap[8 * SP + 4];
#pragma unroll
        for (int ni = 0; ni < 4; ni++) {
            uint32_t bf[2];
            const uint32_t* bp = (const uint32_t*)&vt[ni * 8 + r4][k8 * 8 + c4];
            bf[0] = bp[0];
            bf[1] = bp[4];
            mma_tf32(oacc[ni], af, bf);
        }
    }

#pragma unroll
    for (int ni = 0; ni < 4; ni++) {
        const int d0 = ni * 8 + 2 * c4;
        if (i0 < 49) {
            *(__half2*)(out + ((size_t)w * 49 + i0) * DIM + h * 32 + d0) =
                __floats2half2_rn(oacc[ni][0], oacc[ni][1]);
        }
        if (i1 < 49) {
            *(__half2*)(out + ((size_t)w * 49 + i1) * DIM + h * 32 + d0) =
                __floats2half2_rn(oacc[ni][2], oacc[ni][3]);
        }
    }
}

// ---------------------------------------------------------------------------
extern "C" void kernel_launch(void* const* d_in, const int* in_sizes, int n_in,
                              void* d_out, int out_size)
{
    const float* x      = (const float*)d_in[0];
    const float* mask   = (const float*)d_in[1];
    const float* qkv_w  = (const float*)d_in[2];
    const float* qkv_b  = (const float*)d_in[3];
    const float* proj_w = (const float*)d_in[4];
    const float* proj_b = (const float*)d_in[5];
    const float* bt     = (const float*)d_in[6];
    const int*   rel    = (const int*)d_in[7];
    float* out = (float*)d_out;

    float *qp, *kp, *vp, *combp;
    __half *xh, *atth, *w1h, *w2h;
    cudaGetSymbolAddress((void**)&qp, g_q);
    cudaGetSymbolAddress((void**)&kp, g_k);
    cudaGetSymbolAddress((void**)&vp, g_v);
    cudaGetSymbolAddress((void**)&combp, g_comb);
    cudaGetSymbolAddress((void**)&xh, g_xh);
    cudaGetSymbolAddress((void**)&atth, g_atth);
    cudaGetSymbolAddress((void**)&w1h, g_w1h);
    cudaGetSymbolAddress((void**)&w2h, g_w2h);

    cudaFuncSetAttribute(gemm_f16, cudaFuncAttributeMaxDynamicSharedMemorySize, SMEMH);

    half_pass<<<1184, 256>>>(x, xh, (size_t)MROWS * DIM / 4);
    half_pass<<<112, 256>>>(qkv_w, w1h, (size_t)N1 * KDIM / 4);
    half_pass<<<48, 256>>>(proj_w, w2h, (size_t)DIM * KDIM / 4);
    comb_pre<<<1536, 256>>>(bt, rel, mask, combp);

    dim3 g1(N1 / 128, MROWS / 128);    // 9 x 1568
    gemm_f16<<<g1, 256, SMEMH>>>(xh, w1h, qkv_b, nullptr, qp, kp, vp, 0);

    dim3 ga(NHEAD, BWIN);              // 12 x 4096
    attn_mma<<<ga, 128>>>(qp, kp, vp, combp, atth);

    dim3 g2(DIM / 128, MROWS / 128);   // 3 x 1568
    gemm_f16<<<g2, 256, SMEMH>>>(atth, w2h, proj_b, out, nullptr, nullptr, nullptr, 1);
}

// round 12
// speedup vs baseline: 1.4606x; 1.0842x over previous
#include <cuda_runtime.h>
#include <cuda_fp16.h>
#include <cstdint>

#define DIM     384
#define NHEAD   12
#define NTOK    49
#define BWIN    4096
#define MROWS   (BWIN * NTOK)      // 200704
#define KDIM    384
#define N1      (3 * DIM)          // 1152

// ---------------- static device scratch ----------------
__device__ __half g_q[(size_t)MROWS * DIM];
__device__ __half g_k[(size_t)MROWS * DIM];
__device__ __half g_v[(size_t)MROWS * DIM];
__device__ __half g_xh[(size_t)MROWS * DIM];
__device__ __half g_atth[(size_t)MROWS * DIM];
__device__ __half g_w1h[(size_t)N1 * KDIM];
__device__ __half g_w2h[(size_t)DIM * KDIM];
__device__ float  g_comb[(size_t)NHEAD * 64 * 64 * 64];   // bias+mask, padded

// ---------------- helpers ----------------
__device__ __forceinline__ uint32_t s2u(const void* p) {
    uint32_t a;
    asm("{ .reg .u64 t; cvta.to.shared.u64 t, %1; cvt.u32.u64 %0, t; }" : "=r"(a) : "l"(p));
    return a;
}
__device__ __forceinline__ void cpasync16(uint32_t dst, const void* src) {
    asm volatile("cp.async.cg.shared.global [%0], [%1], 16;" :: "r"(dst), "l"(src));
}
__device__ __forceinline__ void cp_commit() { asm volatile("cp.async.commit_group;" ::: "memory"); }
__device__ __forceinline__ void cp_wait1()  { asm volatile("cp.async.wait_group 1;" ::: "memory"); }
__device__ __forceinline__ void cp_wait0()  { asm volatile("cp.async.wait_group 0;" ::: "memory"); }
__device__ __forceinline__ uint32_t f2tf32(float f) {
    uint32_t u;
    asm("cvt.rna.tf32.f32 %0, %1;" : "=r"(u) : "f"(f));
    return u;
}
__device__ __forceinline__ float rnd_tf32(float f) {
    return __uint_as_float(f2tf32(f));
}
__device__ __forceinline__ void mma_tf32(float* c, const uint32_t* a, const uint32_t* b) {
    asm volatile(
        "mma.sync.aligned.m16n8k8.row.col.f32.tf32.tf32.f32 "
        "{%0,%1,%2,%3}, {%4,%5,%6,%7}, {%8,%9}, {%0,%1,%2,%3};"
        : "+f"(c[0]), "+f"(c[1]), "+f"(c[2]), "+f"(c[3])
        : "r"(a[0]), "r"(a[1]), "r"(a[2]), "r"(a[3]), "r"(b[0]), "r"(b[1]));
}
__device__ __forceinline__ void mma_f16(float* c, const uint32_t* a, const uint32_t* b) {
    asm volatile(
        "mma.sync.aligned.m16n8k16.row.col.f32.f16.f16.f32 "
        "{%0,%1,%2,%3}, {%4,%5,%6,%7}, {%8,%9}, {%0,%1,%2,%3};"
        : "+f"(c[0]), "+f"(c[1]), "+f"(c[2]), "+f"(c[3])
        : "r"(a[0]), "r"(a[1]), "r"(a[2]), "r"(a[3]), "r"(b[0]), "r"(b[1]));
}
__device__ __forceinline__ void ldsm_x4(uint32_t& r0, uint32_t& r1, uint32_t& r2, uint32_t& r3,
                                        uint32_t addr) {
    asm volatile("ldmatrix.sync.aligned.m8n8.x4.shared.b16 {%0,%1,%2,%3}, [%4];"
                 : "=r"(r0), "=r"(r1), "=r"(r2), "=r"(r3) : "r"(addr));
}

// ---------------------------------------------------------------------------
__global__ void half_pass(const float* __restrict__ in, __half* __restrict__ outp, size_t n4)
{
    for (size_t i = blockIdx.x * blockDim.x + threadIdx.x; i < n4;
         i += (size_t)gridDim.x * blockDim.x) {
        float4 v = ((const float4*)in)[i];
        __half2 h0 = __floats2half2_rn(v.x, v.y);
        __half2 h1 = __floats2half2_rn(v.z, v.w);
        uint2 pk = { *(uint32_t*)&h0, *(uint32_t*)&h1 };
        ((uint2*)outp)[i] = pk;
    }
}

// ---------------------------------------------------------------------------
// comb[h][wm][i][j] = bias[h,i,j] + mask[wm,i,j]  (i,j < 49), else -1e30
// ---------------------------------------------------------------------------
__global__ void comb_pre(const float* __restrict__ bt, const int* __restrict__ rel,
                         const float* __restrict__ mask, float* __restrict__ comb)
{
    const int total = NHEAD * 64 * 64 * 64;
    for (int t = blockIdx.x * blockDim.x + threadIdx.x; t < total;
         t += gridDim.x * blockDim.x) {
        int j = t & 63, i = (t >> 6) & 63, wm = (t >> 12) & 63, h = t >> 18;
        float val = -1e30f;
        if (i < NTOK && j < NTOK) {
            int e = i * NTOK + j;
            val = bt[rel[e] * NHEAD + h] + mask[(size_t)wm * 2401 + e];
        }
        comb[t] = val;
    }
}

// ---------------------------------------------------------------------------
// FP16 HMMA GEMM with ldmatrix (proven R11): C = A * B^T + bias.
// mode 0: scatter into q (scaled) / k / v head-major FP16
// mode 1: row-major fp32 out + bias
// ---------------------------------------------------------------------------
#define PADH 72
#define HBUFF (128 * PADH)
#define SMEMH (4 * HBUFF * 2)

__global__ __launch_bounds__(256, 2)
void gemm_f16(const __half* __restrict__ A, const __half* __restrict__ Bm,
              const float* __restrict__ bias, float* __restrict__ outp,
              __half* __restrict__ qo, __half* __restrict__ ko, __half* __restrict__ vo,
              int mode)
{
    extern __shared__ __align__(16) __half smh[];
    const int tid = threadIdx.x;
    const int wid = tid >> 5, lane = tid & 31;
    const int wm = wid & 1, wn = wid >> 1;
    const int bn = blockIdx.x, bm = blockIdx.y;
    const uint32_t smb = s2u(smh);

    const int lrow = tid >> 1;
    const int lcol0 = (tid & 1) * 32;

    auto issue = [&](int ch) {
        const int st = ch & 1;
        const uint32_t da = smb + (uint32_t)(st * 2 * HBUFF) * 2;
        const uint32_t db = da + HBUFF * 2;
        const int kk = ch * 64;
        const __half* ga = A  + (size_t)(bm * 128) * KDIM + kk;
        const __half* gb = Bm + (size_t)(bn * 128) * KDIM + kk;
#pragma unroll
        for (int p = 0; p < 4; p++) {
            int c = lcol0 + p * 8;
            cpasync16(da + (lrow * PADH + c) * 2, ga + (size_t)lrow * KDIM + c);
            cpasync16(db + (lrow * PADH + c) * 2, gb + (size_t)lrow * KDIM + c);
        }
        cp_commit();
    };

    float cacc[4][4][4];
#pragma unroll
    for (int i = 0; i < 4; i++)
#pragma unroll
        for (int j = 0; j < 4; j++)
#pragma unroll
            for (int q = 0; q < 4; q++) cacc[i][j][q] = 0.f;

    issue(0);

    const int a_row = wm * 64 + ((lane >> 3) & 1) * 8 + (lane & 7);
    const int a_col = (lane >> 4) * 8;
    const uint32_t a_off = (uint32_t)(a_row * PADH + a_col) * 2;
    const int b_row = wn * 32 + ((lane >> 4) & 1) * 8 + (lane & 7);
    const int b_col = ((lane >> 3) & 1) * 8;
    const uint32_t b_off = (uint32_t)(b_row * PADH + b_col) * 2;

    for (int ch = 0; ch < 6; ch++) {
        if (ch + 1 < 6) issue(ch + 1);
        if (ch == 5) cp_wait0(); else cp_wait1();
        __syncthreads();

        const uint32_t Asa = smb + (uint32_t)((ch & 1) * 2 * HBUFF) * 2;
        const uint32_t Bsa = Asa + HBUFF * 2;
#pragma unroll
        for (int k16 = 0; k16 < 4; k16++) {
            uint32_t af[4][4], bf[4][2];
            const uint32_t ak = Asa + a_off + k16 * 32;
            const uint32_t bk = Bsa + b_off + k16 * 32;
#pragma unroll
            for (int mi = 0; mi < 4; mi++)
                ldsm_x4(af[mi][0], af[mi][1], af[mi][2], af[mi][3],
                        ak + (uint32_t)(mi * 16 * PADH) * 2);
#pragma unroll
            for (int np = 0; np < 2; np++)
                ldsm_x4(bf[2 * np][0], bf[2 * np][1], bf[2 * np + 1][0], bf[2 * np + 1][1],
                        bk + (uint32_t)(np * 16 * PADH) * 2);
#pragma unroll
            for (int mi = 0; mi < 4; mi++)
#pragma unroll
                for (int ni = 0; ni < 4; ni++)
                    mma_f16(cacc[mi][ni], af[mi], bf[ni]);
        }
        __syncthreads();
    }

    const float qscale = 0.17677669529663687f;
#pragma unroll
    for (int mi = 0; mi < 4; mi++) {
#pragma unroll
        for (int ni = 0; ni < 4; ni++) {
            const int m0 = bm * 128 + wm * 64 + mi * 16 + (lane >> 2);
            const int n0 = bn * 128 + wn * 32 + ni * 8 + 2 * (lane & 3);
            const float b0 = __ldg(bias + n0), b1 = __ldg(bias + n0 + 1);
            float2 v0 = { cacc[mi][ni][0] + b0, cacc[mi][ni][1] + b1 };
            float2 v1 = { cacc[mi][ni][2] + b0, cacc[mi][ni][3] + b1 };
            if (mode == 0) {
                const int arr = n0 / DIM, nin = n0 - arr * DIM;
                const int h = nin >> 5, d = nin & 31;
                if (arr == 0) { v0.x *= qscale; v0.y *= qscale; v1.x *= qscale; v1.y *= qscale; }
                __half* basep = (arr == 0 ? qo : (arr == 1 ? ko : vo));
                int w0 = m0 / NTOK, i0 = m0 - w0 * NTOK;
                *(__half2*)(basep + (((size_t)(w0 * NHEAD + h) * NTOK + i0) << 5) + d) =
                    __floats2half2_rn(v0.x, v0.y);
                int m1 = m0 + 8;
                int w1 = m1 / NTOK, i1 = m1 - w1 * NTOK;
                *(__half2*)(basep + (((size_t)(w1 * NHEAD + h) * NTOK + i1) << 5) + d) =
                    __floats2half2_rn(v1.x, v1.y);
            } else {
                *(float2*)(outp + (size_t)m0 * DIM + n0) = v0;
                *(float2*)(outp + (size_t)(m0 + 8) * DIM + n0) = v1;
            }
        }
    }
}

// ---------------------------------------------------------------------------
// MMA attention (tf32 pipeline, identical to R11 except inputs arrive fp16
// and are widened to fp32 during the smem fill).
// ---------------------------------------------------------------------------
#define QP 36
#define SP 69
#define VP 68

__global__ __launch_bounds__(128, 8)
void attn_mma(const __half* __restrict__ qg, const __half* __restrict__ kg,
              const __half* __restrict__ vg, const float* __restrict__ comb,
              __half* __restrict__ out)
{
    const int h = blockIdx.x, w = blockIdx.y, tid = threadIdx.x;
    const int wid = tid >> 5, lane = tid & 31;
    const int r4 = lane >> 2, c4 = lane & 3;

    __shared__ __align__(16) union SU {
        struct { float qs[64][QP]; float ks[64][QP]; } a;
        float ss[64][SP];
    } u;
    __shared__ __align__(16) float vt[32][VP];

    float (*qs)[QP] = u.a.qs;
    float (*ks)[QP] = u.a.ks;

    for (int t = tid; t < 15 * QP; t += 128) {
        int r = t / QP, c = t - r * QP;
        qs[49 + r][c] = 0.f;
        ks[49 + r][c] = 0.f;
    }
    for (int t = tid; t < 32 * 15; t += 128) {
        int d = t / 15, j = t - d * 15;
        vt[d][49 + j] = 0.f;
    }

    const size_t base = ((size_t)(w * NHEAD + h) * NTOK) << 5;
    for (int t = tid; t < 49 * 16; t += 128) {
        int i = t >> 4, d2 = t & 15;
        float2 qv = __half22float2(*(const __half2*)(qg + base + (i << 5) + 2 * d2));
        float2 kv = __half22float2(*(const __half2*)(kg + base + (i << 5) + 2 * d2));
        float2 vv = __half22float2(*(const __half2*)(vg + base + (i << 5) + 2 * d2));
        qs[i][2 * d2]     = qv.x;
        qs[i][2 * d2 + 1] = qv.y;
        ks[i][2 * d2]     = kv.x;
        ks[i][2 * d2 + 1] = kv.y;
        vt[2 * d2][i]     = vv.x;
        vt[2 * d2 + 1][i] = vv.y;
    }
    __syncthreads();

    const int m0 = wid * 16;

    float sacc[8][4];
#pragma unroll
    for (int ni = 0; ni < 8; ni++)
#pragma unroll
        for (int q = 0; q < 4; q++) sacc[ni][q] = 0.f;

#pragma unroll
    for (int k8 = 0; k8 < 4; k8++) {
        uint32_t af[4];
        const uint32_t* ap = (const uint32_t*)&qs[m0 + r4][k8 * 8 + c4];
        af[0] = ap[0];
        af[1] = ap[8 * QP];
        af[2] = ap[4];
        af[3] = ap[8 * QP + 4];
#pragma unroll
        for (int ni = 0; ni < 8; ni++) {
            uint32_t bf[2];
            const uint32_t* bp = (const uint32_t*)&ks[ni * 8 + r4][k8 * 8 + c4];
            bf[0] = bp[0];
            bf[1] = bp[4];
            mma_tf32(sacc[ni], af, bf);
        }
    }

    const float* cb = comb + (((size_t)h * 64 + (w & 63)) << 12);
    const int i0 = m0 + r4, i1 = i0 + 8;
#pragma unroll
    for (int ni = 0; ni < 8; ni++) {
        const int j0 = ni * 8 + 2 * c4;
        float2 c0 = *(const float2*)(cb + i0 * 64 + j0);
        float2 c1 = *(const float2*)(cb + i1 * 64 + j0);
        sacc[ni][0] += c0.x;
        sacc[ni][1] += c0.y;
        sacc[ni][2] += c1.x;
        sacc[ni][3] += c1.y;
    }

    float mx0 = -1e30f, mx1 = -1e30f;
#pragma unroll
    for (int ni = 0; ni < 8; ni++) {
        mx0 = fmaxf(mx0, fmaxf(sacc[ni][0], sacc[ni][1]));
        mx1 = fmaxf(mx1, fmaxf(sacc[ni][2], sacc[ni][3]));
    }
#pragma unroll
    for (int o = 1; o <= 2; o <<= 1) {
        mx0 = fmaxf(mx0, __shfl_xor_sync(~0u, mx0, o));
        mx1 = fmaxf(mx1, __shfl_xor_sync(~0u, mx1, o));
    }
    float sum0 = 0.f, sum1 = 0.f;
#pragma unroll
    for (int ni = 0; ni < 8; ni++) {
        sacc[ni][0] = __expf(sacc[ni][0] - mx0); sum0 += sacc[ni][0];
        sacc[ni][1] = __expf(sacc[ni][1] - mx0); sum0 += sacc[ni][1];
        sacc[ni][2] = __expf(sacc[ni][2] - mx1); sum1 += sacc[ni][2];
        sacc[ni][3] = __expf(sacc[ni][3] - mx1); sum1 += sacc[ni][3];
    }
#pragma unroll
    for (int o = 1; o <= 2; o <<= 1) {
        sum0 += __shfl_xor_sync(~0u, sum0, o);
        sum1 += __shfl_xor_sync(~0u, sum1, o);
    }
    const float inv0 = 1.0f / sum0, inv1 = 1.0f / sum1;

    __syncthreads();

#pragma unroll
    for (int ni = 0; ni < 8; ni++) {
        const int j0 = ni * 8 + 2 * c4;
        u.ss[i0][j0]     = rnd_tf32(sacc[ni][0] * inv0);
        u.ss[i0][j0 + 1] = rnd_tf32(sacc[ni][1] * inv0);
        u.ss[i1][j0]     = rnd_tf32(sacc[ni][2] * inv1);
        u.ss[i1][j0 + 1] = rnd_tf32(sacc[ni][3] * inv1);
    }
    __syncthreads();

    float oacc[4][4];
#pragma unroll
    for (int ni = 0; ni < 4; ni++)
#pragma unroll
        for (int q = 0; q < 4; q++) oacc[ni][q] = 0.f;

#pragma unroll
    for (int k8 = 0; k8 < 8; k8++) {
        uint32_t af[4];
        const uint32_t* ap = (const uint32_t*)&u.ss[m0 + r4][k8 * 8 + c4];
        af[0] = ap[0];
        af[1] = ap[8 * SP];
        af[2] = ap[4];
        af[3] = ap[8 * SP + 4];
#pragma unroll
        for (int ni = 0; ni < 4; ni++) {
            uint32_t bf[2];
            const uint32_t* bp = (const uint32_t*)&vt[ni * 8 + r4][k8 * 8 + c4];
            bf[0] = bp[0];
            bf[1] = bp[4];
            mma_tf32(oacc[ni], af, bf);
        }
    }

#pragma unroll
    for (int ni = 0; ni < 4; ni++) {
        const int d0 = ni * 8 + 2 * c4;
        if (i0 < 49) {
            *(__half2*)(out + ((size_t)w * 49 + i0) * DIM + h * 32 + d0) =
                __floats2half2_rn(oacc[ni][0], oacc[ni][1]);
        }
        if (i1 < 49) {
            *(__half2*)(out + ((size_t)w * 49 + i1) * DIM + h * 32 + d0) =
                __floats2half2_rn(oacc[ni][2], oacc[ni][3]);
        }
    }
}

// ---------------------------------------------------------------------------
extern "C" void kernel_launch(void* const* d_in, const int* in_sizes, int n_in,
                              void* d_out, int out_size)
{
    const float* x      = (const float*)d_in[0];
    const float* mask   = (const float*)d_in[1];
    const float* qkv_w  = (const float*)d_in[2];
    const float* qkv_b  = (const float*)d_in[3];
    const float* proj_w = (const float*)d_in[4];
    const float* proj_b = (const float*)d_in[5];
    const float* bt     = (const float*)d_in[6];
    const int*   rel    = (const int*)d_in[7];
    float* out = (float*)d_out;

    float *combp;
    __half *qp, *kp, *vp, *xh, *atth, *w1h, *w2h;
    cudaGetSymbolAddress((void**)&qp, g_q);
    cudaGetSymbolAddress((void**)&kp, g_k);
    cudaGetSymbolAddress((void**)&vp, g_v);
    cudaGetSymbolAddress((void**)&combp, g_comb);
    cudaGetSymbolAddress((void**)&xh, g_xh);
    cudaGetSymbolAddress((void**)&atth, g_atth);
    cudaGetSymbolAddress((void**)&w1h, g_w1h);
    cudaGetSymbolAddress((void**)&w2h, g_w2h);

    cudaFuncSetAttribute(gemm_f16, cudaFuncAttributeMaxDynamicSharedMemorySize, SMEMH);

    half_pass<<<1184, 256>>>(x, xh, (size_t)MROWS * DIM / 4);
    half_pass<<<112, 256>>>(qkv_w, w1h, (size_t)N1 * KDIM / 4);
    half_pass<<<48, 256>>>(proj_w, w2h, (size_t)DIM * KDIM / 4);
    comb_pre<<<1536, 256>>>(bt, rel, mask, combp);

    dim3 g1(N1 / 128, MROWS / 128);    // 9 x 1568
    gemm_f16<<<g1, 256, SMEMH>>>(xh, w1h, qkv_b, nullptr, qp, kp, vp, 0);

    dim3 ga(NHEAD, BWIN);              // 12 x 4096
    attn_mma<<<ga, 128>>>(qp, kp, vp, combp, atth);

    dim3 g2(DIM / 128, MROWS / 128);   // 3 x 1568
    gemm_f16<<<g2, 256, SMEMH>>>(atth, w2h, proj_b, out, nullptr, nullptr, nullptr, 1);
}

// round 14
// speedup vs baseline: 1.5461x; 1.0586x over previous
#include <cuda_runtime.h>
#include <cuda_fp16.h>
#include <cstdint>

#define DIM     384
#define NHEAD   12
#define NTOK    49
#define BWIN    4096
#define MROWS   (BWIN * NTOK)      // 200704
#define KDIM    384
#define N1      (3 * DIM)          // 1152

// ---------------- static device scratch ----------------
__device__ __half g_q[(size_t)MROWS * DIM];
__device__ __half g_k[(size_t)MROWS * DIM];
__device__ __half g_v[(size_t)MROWS * DIM];
__device__ __half g_xh[(size_t)MROWS * DIM];
__device__ __half g_atth[(size_t)MROWS * DIM];
__device__ __half g_w1h[(size_t)N1 * KDIM];
__device__ __half g_w2h[(size_t)DIM * KDIM];
__device__ float  g_comb[(size_t)NHEAD * 64 * 64 * 64];   // bias+mask, padded

// ---------------- helpers ----------------
__device__ __forceinline__ uint32_t s2u(const void* p) {
    uint32_t a;
    asm("{ .reg .u64 t; cvta.to.shared.u64 t, %1; cvt.u32.u64 %0, t; }" : "=r"(a) : "l"(p));
    return a;
}
__device__ __forceinline__ void cpasync16(uint32_t dst, const void* src) {
    asm volatile("cp.async.cg.shared.global [%0], [%1], 16;" :: "r"(dst), "l"(src));
}
__device__ __forceinline__ void cp_commit() { asm volatile("cp.async.commit_group;" ::: "memory"); }
__device__ __forceinline__ void cp_wait1()  { asm volatile("cp.async.wait_group 1;" ::: "memory"); }
__device__ __forceinline__ void cp_wait0()  { asm volatile("cp.async.wait_group 0;" ::: "memory"); }
__device__ __forceinline__ void mma_tf32(float* c, const uint32_t* a, const uint32_t* b) {
    asm volatile(
        "mma.sync.aligned.m16n8k8.row.col.f32.tf32.tf32.f32 "
        "{%0,%1,%2,%3}, {%4,%5,%6,%7}, {%8,%9}, {%0,%1,%2,%3};"
        : "+f"(c[0]), "+f"(c[1]), "+f"(c[2]), "+f"(c[3])
        : "r"(a[0]), "r"(a[1]), "r"(a[2]), "r"(a[3]), "r"(b[0]), "r"(b[1]));
}
__device__ __forceinline__ void mma_f16(float* c, const uint32_t* a, const uint32_t* b) {
    asm volatile(
        "mma.sync.aligned.m16n8k16.row.col.f32.f16.f16.f32 "
        "{%0,%1,%2,%3}, {%4,%5,%6,%7}, {%8,%9}, {%0,%1,%2,%3};"
        : "+f"(c[0]), "+f"(c[1]), "+f"(c[2]), "+f"(c[3])
        : "r"(a[0]), "r"(a[1]), "r"(a[2]), "r"(a[3]), "r"(b[0]), "r"(b[1]));
}
__device__ __forceinline__ void ldsm_x4(uint32_t& r0, uint32_t& r1, uint32_t& r2, uint32_t& r3,
                                        uint32_t addr) {
    asm volatile("ldmatrix.sync.aligned.m8n8.x4.shared.b16 {%0,%1,%2,%3}, [%4];"
                 : "=r"(r0), "=r"(r1), "=r"(r2), "=r"(r3) : "r"(addr));
}

// ---------------------------------------------------------------------------
__global__ void half_pass(const float* __restrict__ in, __half* __restrict__ outp, size_t n4)
{
    for (size_t i = blockIdx.x * blockDim.x + threadIdx.x; i < n4;
         i += (size_t)gridDim.x * blockDim.x) {
        float4 v = ((const float4*)in)[i];
        __half2 h0 = __floats2half2_rn(v.x, v.y);
        __half2 h1 = __floats2half2_rn(v.z, v.w);
        uint2 pk = { *(uint32_t*)&h0, *(uint32_t*)&h1 };
        ((uint2*)outp)[i] = pk;
    }
}

// ---------------------------------------------------------------------------
// comb[h][wm][i][j] = bias[h,i,j] + mask[wm,i,j]  (i,j < 49), else -1e30
// ---------------------------------------------------------------------------
__global__ void comb_pre(const float* __restrict__ bt, const int* __restrict__ rel,
                         const float* __restrict__ mask, float* __restrict__ comb)
{
    const int total = NHEAD * 64 * 64 * 64;
    for (int t = blockIdx.x * blockDim.x + threadIdx.x; t < total;
         t += gridDim.x * blockDim.x) {
        int j = t & 63, i = (t >> 6) & 63, wm = (t >> 12) & 63, h = t >> 18;
        float val = -1e30f;
        if (i < NTOK && j < NTOK) {
            int e = i * NTOK + j;
            val = bt[rel[e] * NHEAD + h] + mask[(size_t)wm * 2401 + e];
        }
        comb[t] = val;
    }
}

// ---------------------------------------------------------------------------
// FP16 HMMA GEMM with ldmatrix (proven R11/R12): C = A * B^T + bias.
// mode 0: scatter into q (scaled) / k / v head-major FP16
// mode 1: row-major fp32 out + bias
// ---------------------------------------------------------------------------
#define PADH 72
#define HBUFF (128 * PADH)
#define SMEMH (4 * HBUFF * 2)

__global__ __launch_bounds__(256, 2)
void gemm_f16(const __half* __restrict__ A, const __half* __restrict__ Bm,
              const float* __restrict__ bias, float* __restrict__ outp,
              __half* __restrict__ qo, __half* __restrict__ ko, __half* __restrict__ vo,
              int mode)
{
    extern __shared__ __align__(16) __half smh[];
    const int tid = threadIdx.x;
    const int wid = tid >> 5, lane = tid & 31;
    const int wm = wid & 1, wn = wid >> 1;
    const int bn = blockIdx.x, bm = blockIdx.y;
    const uint32_t smb = s2u(smh);

    const int lrow = tid >> 1;
    const int lcol0 = (tid & 1) * 32;

    auto issue = [&](int ch) {
        const int st = ch & 1;
        const uint32_t da = smb + (uint32_t)(st * 2 * HBUFF) * 2;
        const uint32_t db = da + HBUFF * 2;
        const int kk = ch * 64;
        const __half* ga = A  + (size_t)(bm * 128) * KDIM + kk;
        const __half* gb = Bm + (size_t)(bn * 128) * KDIM + kk;
#pragma unroll
        for (int p = 0; p < 4; p++) {
            int c = lcol0 + p * 8;
            cpasync16(da + (lrow * PADH + c) * 2, ga + (size_t)lrow * KDIM + c);
            cpasync16(db + (lrow * PADH + c) * 2, gb + (size_t)lrow * KDIM + c);
        }
        cp_commit();
    };

    float cacc[4][4][4];
#pragma unroll
    for (int i = 0; i < 4; i++)
#pragma unroll
        for (int j = 0; j < 4; j++)
#pragma unroll
            for (int q = 0; q < 4; q++) cacc[i][j][q] = 0.f;

    issue(0);

    const int a_row = wm * 64 + ((lane >> 3) & 1) * 8 + (lane & 7);
    const int a_col = (lane >> 4) * 8;
    const uint32_t a_off = (uint32_t)(a_row * PADH + a_col) * 2;
    const int b_row = wn * 32 + ((lane >> 4) & 1) * 8 + (lane & 7);
    const int b_col = ((lane >> 3) & 1) * 8;
    const uint32_t b_off = (uint32_t)(b_row * PADH + b_col) * 2;

    for (int ch = 0; ch < 6; ch++) {
        if (ch + 1 < 6) issue(ch + 1);
        if (ch == 5) cp_wait0(); else cp_wait1();
        __syncthreads();

        const uint32_t Asa = smb + (uint32_t)((ch & 1) * 2 * HBUFF) * 2;
        const uint32_t Bsa = Asa + HBUFF * 2;
#pragma unroll
        for (int k16 = 0; k16 < 4; k16++) {
            uint32_t af[4][4], bf[4][2];
            const uint32_t ak = Asa + a_off + k16 * 32;
            const uint32_t bk = Bsa + b_off + k16 * 32;
#pragma unroll
            for (int mi = 0; mi < 4; mi++)
                ldsm_x4(af[mi][0], af[mi][1], af[mi][2], af[mi][3],
                        ak + (uint32_t)(mi * 16 * PADH) * 2);
#pragma unroll
            for (int np = 0; np < 2; np++)
                ldsm_x4(bf[2 * np][0], bf[2 * np][1], bf[2 * np + 1][0], bf[2 * np + 1][1],
                        bk + (uint32_t)(np * 16 * PADH) * 2);
#pragma unroll
            for (int mi = 0; mi < 4; mi++)
#pragma unroll
                for (int ni = 0; ni < 4; ni++)
                    mma_f16(cacc[mi][ni], af[mi], bf[ni]);
        }
        __syncthreads();
    }

    const float qscale = 0.17677669529663687f;
#pragma unroll
    for (int mi = 0; mi < 4; mi++) {
#pragma unroll
        for (int ni = 0; ni < 4; ni++) {
            const int m0 = bm * 128 + wm * 64 + mi * 16 + (lane >> 2);
            const int n0 = bn * 128 + wn * 32 + ni * 8 + 2 * (lane & 3);
            const float b0 = __ldg(bias + n0), b1 = __ldg(bias + n0 + 1);
            float2 v0 = { cacc[mi][ni][0] + b0, cacc[mi][ni][1] + b1 };
            float2 v1 = { cacc[mi][ni][2] + b0, cacc[mi][ni][3] + b1 };
            if (mode == 0) {
                const int arr = n0 / DIM, nin = n0 - arr * DIM;
                const int h = nin >> 5, d = nin & 31;
                if (arr == 0) { v0.x *= qscale; v0.y *= qscale; v1.x *= qscale; v1.y *= qscale; }
                __half* basep = (arr == 0 ? qo : (arr == 1 ? ko : vo));
                int w0 = m0 / NTOK, i0 = m0 - w0 * NTOK;
                *(__half2*)(basep + (((size_t)(w0 * NHEAD + h) * NTOK + i0) << 5) + d) =
                    __floats2half2_rn(v0.x, v0.y);
                int m1 = m0 + 8;
                int w1 = m1 / NTOK, i1 = m1 - w1 * NTOK;
                *(__half2*)(basep + (((size_t)(w1 * NHEAD + h) * NTOK + i1) << 5) + d) =
                    __floats2half2_rn(v1.x, v1.y);
            } else {
                *(float2*)(outp + (size_t)m0 * DIM + n0) = v0;
                *(float2*)(outp + (size_t)(m0 + 8) * DIM + n0) = v1;
            }
        }
    }
}

// ---------------------------------------------------------------------------
// MMA attention: tf32 S-phase (R12-proven) + register-resident P + fp16 PV.
// Block per (h,w), 4 warps. One __syncthreads total after fills.
// ---------------------------------------------------------------------------
#define QP 36     // floats per q/k row
#define VPH 72    // halves per vt row

__global__ __launch_bounds__(128, 8)
void attn_mma(const __half* __restrict__ qg, const __half* __restrict__ kg,
              const __half* __restrict__ vg, const float* __restrict__ comb,
              __half* __restrict__ out)
{
    const int h = blockIdx.x, w = blockIdx.y, tid = threadIdx.x;
    const int wid = tid >> 5, lane = tid & 31;
    const int r4 = lane >> 2, c4 = lane & 3;

    __shared__ __align__(16) float qs[64][QP];     // 9216 B
    __shared__ __align__(16) float ks[64][QP];     // 9216 B
    __shared__ __align__(16) __half vt[32][VPH];   // 4608 B

    // zero pads: q/k rows 49..63, vt cols 49..63
    for (int t = tid; t < 15 * QP; t += 128) {
        int r = t / QP, c = t - r * QP;
        qs[49 + r][c] = 0.f;
        ks[49 + r][c] = 0.f;
    }
    for (int t = tid; t < 32 * 15; t += 128) {
        int d = t / 15, j = t - d * 15;
        vt[d][49 + j] = __ushort_as_half(0);
    }

    const size_t base = ((size_t)(w * NHEAD + h) * NTOK) << 5;
    for (int t = tid; t < 49 * 16; t += 128) {
        int i = t >> 4, d2 = t & 15;
        float2 qv = __half22float2(*(const __half2*)(qg + base + (i << 5) + 2 * d2));
        float2 kv = __half22float2(*(const __half2*)(kg + base + (i << 5) + 2 * d2));
        __half2 vv = *(const __half2*)(vg + base + (i << 5) + 2 * d2);
        qs[i][2 * d2]     = qv.x;
        qs[i][2 * d2 + 1] = qv.y;
        ks[i][2 * d2]     = kv.x;
        ks[i][2 * d2 + 1] = kv.y;
        vt[2 * d2][i]     = __low2half(vv);
        vt[2 * d2 + 1][i] = __high2half(vv);
    }
    __syncthreads();

    const int m0 = wid * 16;

    // ---- S = Q K^T (tf32 MMA; fp16-derived fp32 values are tf32-exact) ----
    float sacc[8][4];
#pragma unroll
    for (int ni = 0; ni < 8; ni++)
#pragma unroll
        for (int q = 0; q < 4; q++) sacc[ni][q] = 0.f;

#pragma unroll
    for (int k8 = 0; k8 < 4; k8++) {
        uint32_t af[4];
        const uint32_t* ap = (const uint32_t*)&qs[m0 + r4][k8 * 8 + c4];
        af[0] = ap[0];
        af[1] = ap[8 * QP];
        af[2] = ap[4];
        af[3] = ap[8 * QP + 4];
#pragma unroll
        for (int ni = 0; ni < 8; ni++) {
            uint32_t bf[2];
            const uint32_t* bp = (const uint32_t*)&ks[ni * 8 + r4][k8 * 8 + c4];
            bf[0] = bp[0];
            bf[1] = bp[4];
            mma_tf32(sacc[ni], af, bf);
        }
    }

    // ---- add comb (bias+mask, padded with -1e30) ----
    const float* cb = comb + (((size_t)h * 64 + (w & 63)) << 12);
    const int i0 = m0 + r4, i1 = i0 + 8;
#pragma unroll
    for (int ni = 0; ni < 8; ni++) {
        const int j0 = ni * 8 + 2 * c4;
        float2 c0 = *(const float2*)(cb + i0 * 64 + j0);
        float2 c1 = *(const float2*)(cb + i1 * 64 + j0);
        sacc[ni][0] += c0.x;
        sacc[ni][1] += c0.y;
        sacc[ni][2] += c1.x;
        sacc[ni][3] += c1.y;
    }

    // ---- register softmax (4-lane groups per row) ----
    float mx0 = -1e30f, mx1 = -1e30f;
#pragma unroll
    for (int ni = 0; ni < 8; ni++) {
        mx0 = fmaxf(mx0, fmaxf(sacc[ni][0], sacc[ni][1]));
        mx1 = fmaxf(mx1, fmaxf(sacc[ni][2], sacc[ni][3]));
    }
#pragma unroll
    for (int o = 1; o <= 2; o <<= 1) {
        mx0 = fmaxf(mx0, __shfl_xor_sync(~0u, mx0, o));
        mx1 = fmaxf(mx1, __shfl_xor_sync(~0u, mx1, o));
    }
    float sum0 = 0.f, sum1 = 0.f;
#pragma unroll
    for (int ni = 0; ni < 8; ni++) {
        sacc[ni][0] = __expf(sacc[ni][0] - mx0); sum0 += sacc[ni][0];
        sacc[ni][1] = __expf(sacc[ni][1] - mx0); sum0 += sacc[ni][1];
        sacc[ni][2] = __expf(sacc[ni][2] - mx1); sum1 += sacc[ni][2];
        sacc[ni][3] = __expf(sacc[ni][3] - mx1); sum1 += sacc[ni][3];
    }
#pragma unroll
    for (int o = 1; o <= 2; o <<= 1) {
        sum0 += __shfl_xor_sync(~0u, sum0, o);
        sum1 += __shfl_xor_sync(~0u, sum1, o);
    }
    const float inv0 = 1.0f / sum0, inv1 = 1.0f / sum1;

    // ---- O = P V : P stays in registers as fp16 A-fragments ----
    // A-fragment identity for k16-step s:
    //   a0 = P[i0][16s+2c4, +1]   = sacc[2s][0..1]   * inv0
    //   a1 = P[i1][16s+2c4, +1]   = sacc[2s][2..3]   * inv1
    //   a2 = P[i0][16s+8+2c4, +1] = sacc[2s+1][0..1] * inv0
    //   a3 = P[i1][16s+8+2c4, +1] = sacc[2s+1][2..3] * inv1
    float oacc[4][4];
#pragma unroll
    for (int ni = 0; ni < 4; ni++)
#pragma unroll
        for (int q = 0; q < 4; q++) oacc[ni][q] = 0.f;

#pragma unroll
    for (int s = 0; s < 4; s++) {
        __half2 a0 = __floats2half2_rn(sacc[2 * s][0] * inv0, sacc[2 * s][1] * inv0);
        __half2 a1 = __floats2half2_rn(sacc[2 * s][2] * inv1, sacc[2 * s][3] * inv1);
        __half2 a2 = __floats2half2_rn(sacc[2 * s + 1][0] * inv0, sacc[2 * s + 1][1] * inv0);
        __half2 a3 = __floats2half2_rn(sacc[2 * s + 1][2] * inv1, sacc[2 * s + 1][3] * inv1);
        uint32_t af[4] = { *(uint32_t*)&a0, *(uint32_t*)&a1, *(uint32_t*)&a2, *(uint32_t*)&a3 };
#pragma unroll
        for (int ni = 0; ni < 4; ni++) {
            uint32_t bf[2];
            const __half* bp = &vt[ni * 8 + r4][s * 16 + 2 * c4];
            bf[0] = *(const uint32_t*)bp;
            bf[1] = *(const uint32_t*)(bp + 8);
            mma_f16(oacc[ni], af, bf);
        }
    }

#pragma unroll
    for (int ni = 0; ni < 4; ni++) {
        const int d0 = ni * 8 + 2 * c4;
        if (i0 < 49) {
            *(__half2*)(out + ((size_t)w * 49 + i0) * DIM + h * 32 + d0) =
                __floats2half2_rn(oacc[ni][0], oacc[ni][1]);
        }
        if (i1 < 49) {
            *(__half2*)(out + ((size_t)w * 49 + i1) * DIM + h * 32 + d0) =
                __floats2half2_rn(oacc[ni][2], oacc[ni][3]);
        }
    }
}

// ---------------------------------------------------------------------------
extern "C" void kernel_launch(void* const* d_in, const int* in_sizes, int n_in,
                              void* d_out, int out_size)
{
    const float* x      = (const float*)d_in[0];
    const float* mask   = (const float*)d_in[1];
    const float* qkv_w  = (const float*)d_in[2];
    const float* qkv_b  = (const float*)d_in[3];
    const float* proj_w = (const float*)d_in[4];
    const float* proj_b = (const float*)d_in[5];
    const float* bt     = (const float*)d_in[6];
    const int*   rel    = (const int*)d_in[7];
    float* out = (float*)d_out;

    float *combp;
    __half *qp, *kp, *vp, *xh, *atth, *w1h, *w2h;
    cudaGetSymbolAddress((void**)&qp, g_q);
    cudaGetSymbolAddress((void**)&kp, g_k);
    cudaGetSymbolAddress((void**)&vp, g_v);
    cudaGetSymbolAddress((void**)&combp, g_comb);
    cudaGetSymbolAddress((void**)&xh, g_xh);
    cudaGetSymbolAddress((void**)&atth, g_atth);
    cudaGetSymbolAddress((void**)&w1h, g_w1h);
    cudaGetSymbolAddress((void**)&w2h, g_w2h);

    cudaFuncSetAttribute(gemm_f16, cudaFuncAttributeMaxDynamicSharedMemorySize, SMEMH);

    half_pass<<<1184, 256>>>(x, xh, (size_t)MROWS * DIM / 4);
    half_pass<<<112, 256>>>(qkv_w, w1h, (size_t)N1 * KDIM / 4);
    half_pass<<<48, 256>>>(proj_w, w2h, (size_t)DIM * KDIM / 4);
    comb_pre<<<1536, 256>>>(bt, rel, mask, combp);

    dim3 g1(N1 / 128, MROWS / 128);    // 9 x 1568
    gemm_f16<<<g1, 256, SMEMH>>>(xh, w1h, qkv_b, nullptr, qp, kp, vp, 0);

    dim3 ga(NHEAD, BWIN);              // 12 x 4096
    attn_mma<<<ga, 128>>>(qp, kp, vp, combp, atth);

    dim3 g2(DIM / 128, MROWS / 128);   // 3 x 1568
    gemm_f16<<<g2, 256, SMEMH>>>(atth, w2h, proj_b, out, nullptr, nullptr, nullptr, 1);
}

// round 16
// speedup vs baseline: 1.6312x; 1.0550x over previous
#include <cuda_runtime.h>
#include <cuda_fp16.h>
#include <cstdint>

#define DIM     384
#define NHEAD   12
#define NTOK    49
#define BWIN    4096
#define MROWS   (BWIN * NTOK)      // 200704
#define KDIM    384
#define N1      (3 * DIM)          // 1152

// ---------------- static device scratch ----------------
__device__ __half g_q[(size_t)MROWS * DIM];
__device__ __half g_k[(size_t)MROWS * DIM];
__device__ __half g_v[(size_t)MROWS * DIM];
__device__ __half g_xh[(size_t)MROWS * DIM];
__device__ __half g_atth[(size_t)MROWS * DIM];
__device__ __half g_w1h[(size_t)N1 * KDIM];
__device__ __half g_w2h[(size_t)DIM * KDIM];
__device__ float  g_comb[(size_t)NHEAD * 64 * 64 * 64];   // bias+mask, padded

// ---------------- helpers ----------------
__device__ __forceinline__ uint32_t s2u(const void* p) {
    uint32_t a;
    asm("{ .reg .u64 t; cvta.to.shared.u64 t, %1; cvt.u32.u64 %0, t; }" : "=r"(a) : "l"(p));
    return a;
}
__device__ __forceinline__ void cpasync16(uint32_t dst, const void* src) {
    asm volatile("cp.async.cg.shared.global [%0], [%1], 16;" :: "r"(dst), "l"(src));
}
__device__ __forceinline__ void cp_commit() { asm volatile("cp.async.commit_group;" ::: "memory"); }
__device__ __forceinline__ void cp_wait1()  { asm volatile("cp.async.wait_group 1;" ::: "memory"); }
__device__ __forceinline__ void cp_wait0()  { asm volatile("cp.async.wait_group 0;" ::: "memory"); }
__device__ __forceinline__ void mma_f16(float* c, const uint32_t* a, const uint32_t* b) {
    asm volatile(
        "mma.sync.aligned.m16n8k16.row.col.f32.f16.f16.f32 "
        "{%0,%1,%2,%3}, {%4,%5,%6,%7}, {%8,%9}, {%0,%1,%2,%3};"
        : "+f"(c[0]), "+f"(c[1]), "+f"(c[2]), "+f"(c[3])
        : "r"(a[0]), "r"(a[1]), "r"(a[2]), "r"(a[3]), "r"(b[0]), "r"(b[1]));
}
__device__ __forceinline__ void ldsm_x4(uint32_t& r0, uint32_t& r1, uint32_t& r2, uint32_t& r3,
                                        uint32_t addr) {
    asm volatile("ldmatrix.sync.aligned.m8n8.x4.shared.b16 {%0,%1,%2,%3}, [%4];"
                 : "=r"(r0), "=r"(r1), "=r"(r2), "=r"(r3) : "r"(addr));
}

// ---------------------------------------------------------------------------
__global__ void half_pass(const float* __restrict__ in, __half* __restrict__ outp, size_t n4)
{
    for (size_t i = blockIdx.x * blockDim.x + threadIdx.x; i < n4;
         i += (size_t)gridDim.x * blockDim.x) {
        float4 v = ((const float4*)in)[i];
        __half2 h0 = __floats2half2_rn(v.x, v.y);
        __half2 h1 = __floats2half2_rn(v.z, v.w);
        uint2 pk = { *(uint32_t*)&h0, *(uint32_t*)&h1 };
        ((uint2*)outp)[i] = pk;
    }
}

// ---------------------------------------------------------------------------
// comb[h][wm][i][j] = bias[h,i,j] + mask[wm,i,j]  (i,j < 49), else -1e30
// ---------------------------------------------------------------------------
__global__ void comb_pre(const float* __restrict__ bt, const int* __restrict__ rel,
                         const float* __restrict__ mask, float* __restrict__ comb)
{
    const int total = NHEAD * 64 * 64 * 64;
    for (int t = blockIdx.x * blockDim.x + threadIdx.x; t < total;
         t += gridDim.x * blockDim.x) {
        int j = t & 63, i = (t >> 6) & 63, wm = (t >> 12) & 63, h = t >> 18;
        float val = -1e30f;
        if (i < NTOK && j < NTOK) {
            int e = i * NTOK + j;
            val = bt[rel[e] * NHEAD + h] + mask[(size_t)wm * 2401 + e];
        }
        comb[t] = val;
    }
}

// ---------------------------------------------------------------------------
// FP16 HMMA GEMM with ldmatrix (proven R11/R12): C = A * B^T + bias.
// mode 0: scatter into q (scaled) / k / v head-major FP16
// mode 1: row-major fp32 out + bias
// ---------------------------------------------------------------------------
#define PADH 72
#define HBUFF (128 * PADH)
#define SMEMH (4 * HBUFF * 2)

__global__ __launch_bounds__(256, 2)
void gemm_f16(const __half* __restrict__ A, const __half* __restrict__ Bm,
              const float* __restrict__ bias, float* __restrict__ outp,
              __half* __restrict__ qo, __half* __restrict__ ko, __half* __restrict__ vo,
              int mode)
{
    extern __shared__ __align__(16) __half smh[];
    const int tid = threadIdx.x;
    const int wid = tid >> 5, lane = tid & 31;
    const int wm = wid & 1, wn = wid >> 1;
    const int bn = blockIdx.x, bm = blockIdx.y;
    const uint32_t smb = s2u(smh);

    const int lrow = tid >> 1;
    const int lcol0 = (tid & 1) * 32;

    auto issue = [&](int ch) {
        const int st = ch & 1;
        const uint32_t da = smb + (uint32_t)(st * 2 * HBUFF) * 2;
        const uint32_t db = da + HBUFF * 2;
        const int kk = ch * 64;
        const __half* ga = A  + (size_t)(bm * 128) * KDIM + kk;
        const __half* gb = Bm + (size_t)(bn * 128) * KDIM + kk;
#pragma unroll
        for (int p = 0; p < 4; p++) {
            int c = lcol0 + p * 8;
            cpasync16(da + (lrow * PADH + c) * 2, ga + (size_t)lrow * KDIM + c);
            cpasync16(db + (lrow * PADH + c) * 2, gb + (size_t)lrow * KDIM + c);
        }
        cp_commit();
    };

    float cacc[4][4][4];
#pragma unroll
    for (int i = 0; i < 4; i++)
#pragma unroll
        for (int j = 0; j < 4; j++)
#pragma unroll
            for (int q = 0; q < 4; q++) cacc[i][j][q] = 0.f;

    issue(0);

    const int a_row = wm * 64 + ((lane >> 3) & 1) * 8 + (lane & 7);
    const int a_col = (lane >> 4) * 8;
    const uint32_t a_off = (uint32_t)(a_row * PADH + a_col) * 2;
    const int b_row = wn * 32 + ((lane >> 4) & 1) * 8 + (lane & 7);
    const int b_col = ((lane >> 3) & 1) * 8;
    const uint32_t b_off = (uint32_t)(b_row * PADH + b_col) * 2;

    for (int ch = 0; ch < 6; ch++) {
        if (ch + 1 < 6) issue(ch + 1);
        if (ch == 5) cp_wait0(); else cp_wait1();
        __syncthreads();

        const uint32_t Asa = smb + (uint32_t)((ch & 1) * 2 * HBUFF) * 2;
        const uint32_t Bsa = Asa + HBUFF * 2;
#pragma unroll
        for (int k16 = 0; k16 < 4; k16++) {
            uint32_t af[4][4], bf[4][2];
            const uint32_t ak = Asa + a_off + k16 * 32;
            const uint32_t bk = Bsa + b_off + k16 * 32;
#pragma unroll
            for (int mi = 0; mi < 4; mi++)
                ldsm_x4(af[mi][0], af[mi][1], af[mi][2], af[mi][3],
                        ak + (uint32_t)(mi * 16 * PADH) * 2);
#pragma unroll
            for (int np = 0; np < 2; np++)
                ldsm_x4(bf[2 * np][0], bf[2 * np][1], bf[2 * np + 1][0], bf[2 * np + 1][1],
                        bk + (uint32_t)(np * 16 * PADH) * 2);
#pragma unroll
            for (int mi = 0; mi < 4; mi++)
#pragma unroll
                for (int ni = 0; ni < 4; ni++)
                    mma_f16(cacc[mi][ni], af[mi], bf[ni]);
        }
        __syncthreads();
    }

    const float qscale = 0.17677669529663687f;
#pragma unroll
    for (int mi = 0; mi < 4; mi++) {
#pragma unroll
        for (int ni = 0; ni < 4; ni++) {
            const int m0 = bm * 128 + wm * 64 + mi * 16 + (lane >> 2);
            const int n0 = bn * 128 + wn * 32 + ni * 8 + 2 * (lane & 3);
            const float b0 = __ldg(bias + n0), b1 = __ldg(bias + n0 + 1);
            float2 v0 = { cacc[mi][ni][0] + b0, cacc[mi][ni][1] + b1 };
            float2 v1 = { cacc[mi][ni][2] + b0, cacc[mi][ni][3] + b1 };
            if (mode == 0) {
                const int arr = n0 / DIM, nin = n0 - arr * DIM;
                const int h = nin >> 5, d = nin & 31;
                if (arr == 0) { v0.x *= qscale; v0.y *= qscale; v1.x *= qscale; v1.y *= qscale; }
                __half* basep = (arr == 0 ? qo : (arr == 1 ? ko : vo));
                int w0 = m0 / NTOK, i0 = m0 - w0 * NTOK;
                *(__half2*)(basep + (((size_t)(w0 * NHEAD + h) * NTOK + i0) << 5) + d) =
                    __floats2half2_rn(v0.x, v0.y);
                int m1 = m0 + 8;
                int w1 = m1 / NTOK, i1 = m1 - w1 * NTOK;
                *(__half2*)(basep + (((size_t)(w1 * NHEAD + h) * NTOK + i1) << 5) + d) =
                    __floats2half2_rn(v1.x, v1.y);
            } else {
                *(float2*)(outp + (size_t)m0 * DIM + n0) = v0;
                *(float2*)(outp + (size_t)(m0 + 8) * DIM + n0) = v1;
            }
        }
    }
}

// ---------------------------------------------------------------------------
// Attention: fp16 S-phase (direct u32 fragment loads) + register P + fp16 PV.
// Block per (h,w), 4 warps, one __syncthreads after fills.
// ---------------------------------------------------------------------------
#define QPH 40    // halves per q/k row (80 B; 16B-aligned rows, conflict-free)
#define VPH 72    // halves per vt row

__global__ __launch_bounds__(128, 8)
void attn_mma(const __half* __restrict__ qg, const __half* __restrict__ kg,
              const __half* __restrict__ vg, const float* __restrict__ comb,
              __half* __restrict__ out)
{
    const int h = blockIdx.x, w = blockIdx.y, tid = threadIdx.x;
    const int wid = tid >> 5, lane = tid & 31;
    const int r4 = lane >> 2, c4 = lane & 3;

    __shared__ __align__(16) __half qs[64][QPH];   // 5120 B
    __shared__ __align__(16) __half ks[64][QPH];   // 5120 B
    __shared__ __align__(16) __half vt[32][VPH];   // 4608 B

    // zero pads: q/k rows 49..63 (cols 0..31), vt cols 49..63
    for (int t = tid; t < 15 * 32; t += 128) {
        int r = t >> 5, c = t & 31;
        qs[49 + r][c] = __ushort_as_half(0);
        ks[49 + r][c] = __ushort_as_half(0);
    }
    for (int t = tid; t < 32 * 15; t += 128) {
        int d = t / 15, j = t - d * 15;
        vt[d][49 + j] = __ushort_as_half(0);
    }

    // fills: q/k as uint4 (8 halves) copies; v transposed scalar
    const size_t base = ((size_t)(w * NHEAD + h) * NTOK) << 5;
    for (int t = tid; t < 49 * 4; t += 128) {
        int i = t >> 2, d8 = (t & 3) * 8;
        *(uint4*)&qs[i][d8] = *(const uint4*)(qg + base + (i << 5) + d8);
        *(uint4*)&ks[i][d8] = *(const uint4*)(kg + base + (i << 5) + d8);
        uint4 vv = *(const uint4*)(vg + base + (i << 5) + d8);
        const __half* vh = (const __half*)&vv;
#pragma unroll
        for (int e = 0; e < 8; e++) vt[d8 + e][i] = vh[e];
    }
    __syncthreads();

    const int m0 = wid * 16;
    const int i0 = m0 + r4, i1 = i0 + 8;

    // ---- S = Q K^T : fp16 m16n8k16, 2 k16 steps, direct u32 fragment loads ----
    float sacc[8][4];
#pragma unroll
    for (int ni = 0; ni < 8; ni++)
#pragma unroll
        for (int q = 0; q < 4; q++) sacc[ni][q] = 0.f;

#pragma unroll
    for (int s = 0; s < 2; s++) {
        uint32_t af[4];
        const int kc = s * 16 + 2 * c4;
        af[0] = *(const uint32_t*)&qs[i0][kc];
        af[1] = *(const uint32_t*)&qs[i1][kc];
        af[2] = *(const uint32_t*)&qs[i0][kc + 8];
        af[3] = *(const uint32_t*)&qs[i1][kc + 8];
#pragma unroll
        for (int ni = 0; ni < 8; ni++) {
            uint32_t bf[2];
            const __half* bp = &ks[ni * 8 + r4][kc];
            bf[0] = *(const uint32_t*)bp;
            bf[1] = *(const uint32_t*)(bp + 8);
            mma_f16(sacc[ni], af, bf);
        }
    }

    // ---- add comb (bias+mask, padded with -1e30) ----
    const float* cb = comb + (((size_t)h * 64 + (w & 63)) << 12);
#pragma unroll
    for (int ni = 0; ni < 8; ni++) {
        const int j0 = ni * 8 + 2 * c4;
        float2 c0 = *(const float2*)(cb + i0 * 64 + j0);
        float2 c1 = *(const float2*)(cb + i1 * 64 + j0);
        sacc[ni][0] += c0.x;
        sacc[ni][1] += c0.y;
        sacc[ni][2] += c1.x;
        sacc[ni][3] += c1.y;
    }

    // ---- register softmax (4-lane groups per row) ----
    float mx0 = -1e30f, mx1 = -1e30f;
#pragma unroll
    for (int ni = 0; ni < 8; ni++) {
        mx0 = fmaxf(mx0, fmaxf(sacc[ni][0], sacc[ni][1]));
        mx1 = fmaxf(mx1, fmaxf(sacc[ni][2], sacc[ni][3]));
    }
#pragma unroll
    for (int o = 1; o <= 2; o <<= 1) {
        mx0 = fmaxf(mx0, __shfl_xor_sync(~0u, mx0, o));
        mx1 = fmaxf(mx1, __shfl_xor_sync(~0u, mx1, o));
    }
    float sum0 = 0.f, sum1 = 0.f;
#pragma unroll
    for (int ni = 0; ni < 8; ni++) {
        sacc[ni][0] = __expf(sacc[ni][0] - mx0); sum0 += sacc[ni][0];
        sacc[ni][1] = __expf(sacc[ni][1] - mx0); sum0 += sacc[ni][1];
        sacc[ni][2] = __expf(sacc[ni][2] - mx1); sum1 += sacc[ni][2];
        sacc[ni][3] = __expf(sacc[ni][3] - mx1); sum1 += sacc[ni][3];
    }
#pragma unroll
    for (int o = 1; o <= 2; o <<= 1) {
        sum0 += __shfl_xor_sync(~0u, sum0, o);
        sum1 += __shfl_xor_sync(~0u, sum1, o);
    }
    const float inv0 = 1.0f / sum0, inv1 = 1.0f / sum1;

    // ---- O = P V : P stays in registers as fp16 A-fragments (R14-proven) ----
    float oacc[4][4];
#pragma unroll
    for (int ni = 0; ni < 4; ni++)
#pragma unroll
        for (int q = 0; q < 4; q++) oacc[ni][q] = 0.f;

#pragma unroll
    for (int s = 0; s < 4; s++) {
        __half2 a0 = __floats2half2_rn(sacc[2 * s][0] * inv0, sacc[2 * s][1] * inv0);
        __half2 a1 = __floats2half2_rn(sacc[2 * s][2] * inv1, sacc[2 * s][3] * inv1);
        __half2 a2 = __floats2half2_rn(sacc[2 * s + 1][0] * inv0, sacc[2 * s + 1][1] * inv0);
        __half2 a3 = __floats2half2_rn(sacc[2 * s + 1][2] * inv1, sacc[2 * s + 1][3] * inv1);
        uint32_t af[4] = { *(uint32_t*)&a0, *(uint32_t*)&a1, *(uint32_t*)&a2, *(uint32_t*)&a3 };
#pragma unroll
        for (int ni = 0; ni < 4; ni++) {
            uint32_t bf[2];
            const __half* bp = &vt[ni * 8 + r4][s * 16 + 2 * c4];
            bf[0] = *(const uint32_t*)bp;
            bf[1] = *(const uint32_t*)(bp + 8);
            mma_f16(oacc[ni], af, bf);
        }
    }

#pragma unroll
    for (int ni = 0; ni < 4; ni++) {
        const int d0 = ni * 8 + 2 * c4;
        if (i0 < 49) {
            *(__half2*)(out + ((size_t)w * 49 + i0) * DIM + h * 32 + d0) =
                __floats2half2_rn(oacc[ni][0], oacc[ni][1]);
        }
        if (i1 < 49) {
            *(__half2*)(out + ((size_t)w * 49 + i1) * DIM + h * 32 + d0) =
                __floats2half2_rn(oacc[ni][2], oacc[ni][3]);
        }
    }
}

// ---------------------------------------------------------------------------
extern "C" void kernel_launch(void* const* d_in, const int* in_sizes, int n_in,
                              void* d_out, int out_size)
{
    const float* x      = (const float*)d_in[0];
    const float* mask   = (const float*)d_in[1];
    const float* qkv_w  = (const float*)d_in[2];
    const float* qkv_b  = (const float*)d_in[3];
    const float* proj_w = (const float*)d_in[4];
    const float* proj_b = (const float*)d_in[5];
    const float* bt     = (const float*)d_in[6];
    const int*   rel    = (const int*)d_in[7];
    float* out = (float*)d_out;

    float *combp;
    __half *qp, *kp, *vp, *xh, *atth, *w1h, *w2h;
    cudaGetSymbolAddress((void**)&qp, g_q);
    cudaGetSymbolAddress((void**)&kp, g_k);
    cudaGetSymbolAddress((void**)&vp, g_v);
    cudaGetSymbolAddress((void**)&combp, g_comb);
    cudaGetSymbolAddress((void**)&xh, g_xh);
    cudaGetSymbolAddress((void**)&atth, g_atth);
    cudaGetSymbolAddress((void**)&w1h, g_w1h);
    cudaGetSymbolAddress((void**)&w2h, g_w2h);

    cudaFuncSetAttribute(gemm_f16, cudaFuncAttributeMaxDynamicSharedMemorySize, SMEMH);

    half_pass<<<1184, 256>>>(x, xh, (size_t)MROWS * DIM / 4);
    half_pass<<<112, 256>>>(qkv_w, w1h, (size_t)N1 * KDIM / 4);
    half_pass<<<48, 256>>>(proj_w, w2h, (size_t)DIM * KDIM / 4);
    comb_pre<<<1536, 256>>>(bt, rel, mask, combp);

    dim3 g1(N1 / 128, MROWS / 128);    // 9 x 1568
    gemm_f16<<<g1, 256, SMEMH>>>(xh, w1h, qkv_b, nullptr, qp, kp, vp, 0);

    dim3 ga(NHEAD, BWIN);              // 12 x 4096
    attn_mma<<<ga, 128>>>(qp, kp, vp, combp, atth);

    dim3 g2(DIM / 128, MROWS / 128);   // 3 x 1568
    gemm_f16<<<g2, 256, SMEMH>>>(atth, w2h, proj_b, out, nullptr, nullptr, nullptr, 1);
}

// round 17
// speedup vs baseline: 1.6314x; 1.0001x over previous
#include <cuda_runtime.h>
#include <cuda_fp16.h>
#include <cstdint>

#define DIM     384
#define NHEAD   12
#define NTOK    49
#define BWIN    4096
#define MROWS   (BWIN * NTOK)      // 200704
#define KDIM    384
#define N1      (3 * DIM)          // 1152

// ---------------- static device scratch ----------------
__device__ __half g_q[(size_t)MROWS * DIM];
__device__ __half g_k[(size_t)MROWS * DIM];
__device__ __half g_v[(size_t)MROWS * DIM];
__device__ __half g_xh[(size_t)MROWS * DIM];
__device__ __half g_atth[(size_t)MROWS * DIM];
__device__ __half g_w1h[(size_t)N1 * KDIM];
__device__ __half g_w2h[(size_t)DIM * KDIM];
__device__ __half g_combh[(size_t)NHEAD * 64 * 64 * 64];   // bias+mask, fp16, padded

// ---------------- helpers ----------------
__device__ __forceinline__ uint32_t s2u(const void* p) {
    uint32_t a;
    asm("{ .reg .u64 t; cvta.to.shared.u64 t, %1; cvt.u32.u64 %0, t; }" : "=r"(a) : "l"(p));
    return a;
}
__device__ __forceinline__ void cpasync16(uint32_t dst, const void* src) {
    asm volatile("cp.async.cg.shared.global [%0], [%1], 16;" :: "r"(dst), "l"(src));
}
__device__ __forceinline__ void cp_commit() { asm volatile("cp.async.commit_group;" ::: "memory"); }
__device__ __forceinline__ void cp_wait1()  { asm volatile("cp.async.wait_group 1;" ::: "memory"); }
__device__ __forceinline__ void cp_wait0()  { asm volatile("cp.async.wait_group 0;" ::: "memory"); }
__device__ __forceinline__ void mma_f16(float* c, const uint32_t* a, const uint32_t* b) {
    asm volatile(
        "mma.sync.aligned.m16n8k16.row.col.f32.f16.f16.f32 "
        "{%0,%1,%2,%3}, {%4,%5,%6,%7}, {%8,%9}, {%0,%1,%2,%3};"
        : "+f"(c[0]), "+f"(c[1]), "+f"(c[2]), "+f"(c[3])
        : "r"(a[0]), "r"(a[1]), "r"(a[2]), "r"(a[3]), "r"(b[0]), "r"(b[1]));
}
__device__ __forceinline__ void ldsm_x4(uint32_t& r0, uint32_t& r1, uint32_t& r2, uint32_t& r3,
                                        uint32_t addr) {
    asm volatile("ldmatrix.sync.aligned.m8n8.x4.shared.b16 {%0,%1,%2,%3}, [%4];"
                 : "=r"(r0), "=r"(r1), "=r"(r2), "=r"(r3) : "r"(addr));
}

// ---------------------------------------------------------------------------
__global__ void half_pass(const float* __restrict__ in, __half* __restrict__ outp, size_t n4)
{
    for (size_t i = blockIdx.x * blockDim.x + threadIdx.x; i < n4;
         i += (size_t)gridDim.x * blockDim.x) {
        float4 v = ((const float4*)in)[i];
        __half2 h0 = __floats2half2_rn(v.x, v.y);
        __half2 h1 = __floats2half2_rn(v.z, v.w);
        uint2 pk = { *(uint32_t*)&h0, *(uint32_t*)&h1 };
        ((uint2*)outp)[i] = pk;
    }
}

// ---------------------------------------------------------------------------
// combh[h][wm][i][j] = fp16(bias[h,i,j] + mask[wm,i,j])  (i,j < 49), else -60000
// ---------------------------------------------------------------------------
__global__ void comb_pre(const float* __restrict__ bt, const int* __restrict__ rel,
                         const float* __restrict__ mask, __half* __restrict__ comb)
{
    const int total = NHEAD * 64 * 64 * 64;
    for (int t = blockIdx.x * blockDim.x + threadIdx.x; t < total;
         t += gridDim.x * blockDim.x) {
        int j = t & 63, i = (t >> 6) & 63, wm = (t >> 12) & 63, h = t >> 18;
        float val = -60000.f;
        if (i < NTOK && j < NTOK) {
            int e = i * NTOK + j;
            val = bt[rel[e] * NHEAD + h] + mask[(size_t)wm * 2401 + e];
        }
        comb[t] = __float2half_rn(val);
    }
}

// ---------------------------------------------------------------------------
// FP16 HMMA GEMM with ldmatrix (proven R11/R12): C = A * B^T + bias.
// mode 0: scatter into q (scaled) / k / v head-major FP16
// mode 1: row-major fp32 out + bias
// ---------------------------------------------------------------------------
#define PADH 72
#define HBUFF (128 * PADH)
#define SMEMH (4 * HBUFF * 2)

__global__ __launch_bounds__(256, 2)
void gemm_f16(const __half* __restrict__ A, const __half* __restrict__ Bm,
              const float* __restrict__ bias, float* __restrict__ outp,
              __half* __restrict__ qo, __half* __restrict__ ko, __half* __restrict__ vo,
              int mode)
{
    extern __shared__ __align__(16) __half smh[];
    const int tid = threadIdx.x;
    const int wid = tid >> 5, lane = tid & 31;
    const int wm = wid & 1, wn = wid >> 1;
    const int bn = blockIdx.x, bm = blockIdx.y;
    const uint32_t smb = s2u(smh);

    const int lrow = tid >> 1;
    const int lcol0 = (tid & 1) * 32;

    auto issue = [&](int ch) {
        const int st = ch & 1;
        const uint32_t da = smb + (uint32_t)(st * 2 * HBUFF) * 2;
        const uint32_t db = da + HBUFF * 2;
        const int kk = ch * 64;
        const __half* ga = A  + (size_t)(bm * 128) * KDIM + kk;
        const __half* gb = Bm + (size_t)(bn * 128) * KDIM + kk;
#pragma unroll
        for (int p = 0; p < 4; p++) {
            int c = lcol0 + p * 8;
            cpasync16(da + (lrow * PADH + c) * 2, ga + (size_t)lrow * KDIM + c);
            cpasync16(db + (lrow * PADH + c) * 2, gb + (size_t)lrow * KDIM + c);
        }
        cp_commit();
    };

    float cacc[4][4][4];
#pragma unroll
    for (int i = 0; i < 4; i++)
#pragma unroll
        for (int j = 0; j < 4; j++)
#pragma unroll
            for (int q = 0; q < 4; q++) cacc[i][j][q] = 0.f;

    issue(0);

    const int a_row = wm * 64 + ((lane >> 3) & 1) * 8 + (lane & 7);
    const int a_col = (lane >> 4) * 8;
    const uint32_t a_off = (uint32_t)(a_row * PADH + a_col) * 2;
    const int b_row = wn * 32 + ((lane >> 4) & 1) * 8 + (lane & 7);
    const int b_col = ((lane >> 3) & 1) * 8;
    const uint32_t b_off = (uint32_t)(b_row * PADH + b_col) * 2;

    for (int ch = 0; ch < 6; ch++) {
        if (ch + 1 < 6) issue(ch + 1);
        if (ch == 5) cp_wait0(); else cp_wait1();
        __syncthreads();

        const uint32_t Asa = smb + (uint32_t)((ch & 1) * 2 * HBUFF) * 2;
        const uint32_t Bsa = Asa + HBUFF * 2;
#pragma unroll
        for (int k16 = 0; k16 < 4; k16++) {
            uint32_t af[4][4], bf[4][2];
            const uint32_t ak = Asa + a_off + k16 * 32;
            const uint32_t bk = Bsa + b_off + k16 * 32;
#pragma unroll
            for (int mi = 0; mi < 4; mi++)
                ldsm_x4(af[mi][0], af[mi][1], af[mi][2], af[mi][3],
                        ak + (uint32_t)(mi * 16 * PADH) * 2);
#pragma unroll
            for (int np = 0; np < 2; np++)
                ldsm_x4(bf[2 * np][0], bf[2 * np][1], bf[2 * np + 1][0], bf[2 * np + 1][1],
                        bk + (uint32_t)(np * 16 * PADH) * 2);
#pragma unroll
            for (int mi = 0; mi < 4; mi++)
#pragma unroll
                for (int ni = 0; ni < 4; ni++)
                    mma_f16(cacc[mi][ni], af[mi], bf[ni]);
        }
        __syncthreads();
    }

    const float qscale = 0.17677669529663687f;
#pragma unroll
    for (int mi = 0; mi < 4; mi++) {
#pragma unroll
        for (int ni = 0; ni < 4; ni++) {
            const int m0 = bm * 128 + wm * 64 + mi * 16 + (lane >> 2);
            const int n0 = bn * 128 + wn * 32 + ni * 8 + 2 * (lane & 3);
            const float b0 = __ldg(bias + n0), b1 = __ldg(bias + n0 + 1);
            float2 v0 = { cacc[mi][ni][0] + b0, cacc[mi][ni][1] + b1 };
            float2 v1 = { cacc[mi][ni][2] + b0, cacc[mi][ni][3] + b1 };
            if (mode == 0) {
                const int arr = n0 / DIM, nin = n0 - arr * DIM;
                const int h = nin >> 5, d = nin & 31;
                if (arr == 0) { v0.x *= qscale; v0.y *= qscale; v1.x *= qscale; v1.y *= qscale; }
                __half* basep = (arr == 0 ? qo : (arr == 1 ? ko : vo));
                int w0 = m0 / NTOK, i0 = m0 - w0 * NTOK;
                *(__half2*)(basep + (((size_t)(w0 * NHEAD + h) * NTOK + i0) << 5) + d) =
                    __floats2half2_rn(v0.x, v0.y);
                int m1 = m0 + 8;
                int w1 = m1 / NTOK, i1 = m1 - w1 * NTOK;
                *(__half2*)(basep + (((size_t)(w1 * NHEAD + h) * NTOK + i1) << 5) + d) =
                    __floats2half2_rn(v1.x, v1.y);
            } else {
                *(float2*)(outp + (size_t)m0 * DIM + n0) = v0;
                *(float2*)(outp + (size_t)(m0 + 8) * DIM + n0) = v1;
            }
        }
    }
}

// ---------------------------------------------------------------------------
// Attention: fp16 S-phase (direct u32 fragment loads, R15-proven) +
// register P + fp16 PV. comb now fp16.
// ---------------------------------------------------------------------------
#define QPH 40    // halves per q/k row (80 B; 16B-aligned rows, conflict-free)
#define VPH 72    // halves per vt row

__global__ __launch_bounds__(128, 8)
void attn_mma(const __half* __restrict__ qg, const __half* __restrict__ kg,
              const __half* __restrict__ vg, const __half* __restrict__ comb,
              __half* __restrict__ out)
{
    const int h = blockIdx.x, w = blockIdx.y, tid = threadIdx.x;
    const int wid = tid >> 5, lane = tid & 31;
    const int r4 = lane >> 2, c4 = lane & 3;

    __shared__ __align__(16) __half qs[64][QPH];   // 5120 B
    __shared__ __align__(16) __half ks[64][QPH];   // 5120 B
    __shared__ __align__(16) __half vt[32][VPH];   // 4608 B

    // zero pads: q/k rows 49..63 (cols 0..31), vt cols 49..63
    for (int t = tid; t < 15 * 32; t += 128) {
        int r = t >> 5, c = t & 31;
        qs[49 + r][c] = __ushort_as_half(0);
        ks[49 + r][c] = __ushort_as_half(0);
    }
    for (int t = tid; t < 32 * 15; t += 128) {
        int d = t / 15, j = t - d * 15;
        vt[d][49 + j] = __ushort_as_half(0);
    }

    // fills: q/k as uint4 (8 halves) copies; v transposed scalar
    const size_t base = ((size_t)(w * NHEAD + h) * NTOK) << 5;
    for (int t = tid; t < 49 * 4; t += 128) {
        int i = t >> 2, d8 = (t & 3) * 8;
        *(uint4*)&qs[i][d8] = *(const uint4*)(qg + base + (i << 5) + d8);
        *(uint4*)&ks[i][d8] = *(const uint4*)(kg + base + (i << 5) + d8);
        uint4 vv = *(const uint4*)(vg + base + (i << 5) + d8);
        const __half* vh = (const __half*)&vv;
#pragma unroll
        for (int e = 0; e < 8; e++) vt[d8 + e][i] = vh[e];
    }
    __syncthreads();

    const int m0 = wid * 16;
    const int i0 = m0 + r4, i1 = i0 + 8;

    // ---- S = Q K^T : fp16 m16n8k16, 2 k16 steps, direct u32 fragment loads ----
    float sacc[8][4];
#pragma unroll
    for (int ni = 0; ni < 8; ni++)
#pragma unroll
        for (int q = 0; q < 4; q++) sacc[ni][q] = 0.f;

#pragma unroll
    for (int s = 0; s < 2; s++) {
        uint32_t af[4];
        const int kc = s * 16 + 2 * c4;
        af[0] = *(const uint32_t*)&qs[i0][kc];
        af[1] = *(const uint32_t*)&qs[i1][kc];
        af[2] = *(const uint32_t*)&qs[i0][kc + 8];
        af[3] = *(const uint32_t*)&qs[i1][kc + 8];
#pragma unroll
        for (int ni = 0; ni < 8; ni++) {
            uint32_t bf[2];
            const __half* bp = &ks[ni * 8 + r4][kc];
            bf[0] = *(const uint32_t*)bp;
            bf[1] = *(const uint32_t*)(bp + 8);
            mma_f16(sacc[ni], af, bf);
        }
    }

    // ---- add comb (fp16 bias+mask, padded with -60000) ----
    const __half* cb = comb + (((size_t)h * 64 + (w & 63)) << 12);
#pragma unroll
    for (int ni = 0; ni < 8; ni++) {
        const int j0 = ni * 8 + 2 * c4;
        float2 c0 = __half22float2(*(const __half2*)(cb + i0 * 64 + j0));
        float2 c1 = __half22float2(*(const __half2*)(cb + i1 * 64 + j0));
        sacc[ni][0] += c0.x;
        sacc[ni][1] += c0.y;
        sacc[ni][2] += c1.x;
        sacc[ni][3] += c1.y;
    }

    // ---- register softmax (4-lane groups per row) ----
    float mx0 = -1e30f, mx1 = -1e30f;
#pragma unroll
    for (int ni = 0; ni < 8; ni++) {
        mx0 = fmaxf(mx0, fmaxf(sacc[ni][0], sacc[ni][1]));
        mx1 = fmaxf(mx1, fmaxf(sacc[ni][2], sacc[ni][3]));
    }
#pragma unroll
    for (int o = 1; o <= 2; o <<= 1) {
        mx0 = fmaxf(mx0, __shfl_xor_sync(~0u, mx0, o));
        mx1 = fmaxf(mx1, __shfl_xor_sync(~0u, mx1, o));
    }
    float sum0 = 0.f, sum1 = 0.f;
#pragma unroll
    for (int ni = 0; ni < 8; ni++) {
        sacc[ni][0] = __expf(sacc[ni][0] - mx0); sum0 += sacc[ni][0];
        sacc[ni][1] = __expf(sacc[ni][1] - mx0); sum0 += sacc[ni][1];
        sacc[ni][2] = __expf(sacc[ni][2] - mx1); sum1 += sacc[ni][2];
        sacc[ni][3] = __expf(sacc[ni][3] - mx1); sum1 += sacc[ni][3];
    }
#pragma unroll
    for (int o = 1; o <= 2; o <<= 1) {
        sum0 += __shfl_xor_sync(~0u, sum0, o);
        sum1 += __shfl_xor_sync(~0u, sum1, o);
    }
    const float inv0 = 1.0f / sum0, inv1 = 1.0f / sum1;

    // ---- O = P V : P stays in registers as fp16 A-fragments (R14-proven) ----
    float oacc[4][4];
#pragma unroll
    for (int ni = 0; ni < 4; ni++)
#pragma unroll
        for (int q = 0; q < 4; q++) oacc[ni][q] = 0.f;

#pragma unroll
    for (int s = 0; s < 4; s++) {
        __half2 a0 = __floats2half2_rn(sacc[2 * s][0] * inv0, sacc[2 * s][1] * inv0);
        __half2 a1 = __floats2half2_rn(sacc[2 * s][2] * inv1, sacc[2 * s][3] * inv1);
        __half2 a2 = __floats2half2_rn(sacc[2 * s + 1][0] * inv0, sacc[2 * s + 1][1] * inv0);
        __half2 a3 = __floats2half2_rn(sacc[2 * s + 1][2] * inv1, sacc[2 * s + 1][3] * inv1);
        uint32_t af[4] = { *(uint32_t*)&a0, *(uint32_t*)&a1, *(uint32_t*)&a2, *(uint32_t*)&a3 };
#pragma unroll
        for (int ni = 0; ni < 4; ni++) {
            uint32_t bf[2];
            const __half* bp = &vt[ni * 8 + r4][s * 16 + 2 * c4];
            bf[0] = *(const uint32_t*)bp;
            bf[1] = *(const uint32_t*)(bp + 8);
            mma_f16(oacc[ni], af, bf);
        }
    }

#pragma unroll
    for (int ni = 0; ni < 4; ni++) {
        const int d0 = ni * 8 + 2 * c4;
        if (i0 < 49) {
            *(__half2*)(out + ((size_t)w * 49 + i0) * DIM + h * 32 + d0) =
                __floats2half2_rn(oacc[ni][0], oacc[ni][1]);
        }
        if (i1 < 49) {
            *(__half2*)(out + ((size_t)w * 49 + i1) * DIM + h * 32 + d0) =
                __floats2half2_rn(oacc[ni][2], oacc[ni][3]);
        }
    }
}

// ---------------------------------------------------------------------------
extern "C" void kernel_launch(void* const* d_in, const int* in_sizes, int n_in,
                              void* d_out, int out_size)
{
    const float* x      = (const float*)d_in[0];
    const float* mask   = (const float*)d_in[1];
    const float* qkv_w  = (const float*)d_in[2];
    const float* qkv_b  = (const float*)d_in[3];
    const float* proj_w = (const float*)d_in[4];
    const float* proj_b = (const float*)d_in[5];
    const float* bt     = (const float*)d_in[6];
    const int*   rel    = (const int*)d_in[7];
    float* out = (float*)d_out;

    __half *qp, *kp, *vp, *xh, *atth, *w1h, *w2h, *combp;
    cudaGetSymbolAddress((void**)&qp, g_q);
    cudaGetSymbolAddress((void**)&kp, g_k);
    cudaGetSymbolAddress((void**)&vp, g_v);
    cudaGetSymbolAddress((void**)&combp, g_combh);
    cudaGetSymbolAddress((void**)&xh, g_xh);
    cudaGetSymbolAddress((void**)&atth, g_atth);
    cudaGetSymbolAddress((void**)&w1h, g_w1h);
    cudaGetSymbolAddress((void**)&w2h, g_w2h);

    cudaFuncSetAttribute(gemm_f16, cudaFuncAttributeMaxDynamicSharedMemorySize, SMEMH);

    half_pass<<<1184, 256>>>(x, xh, (size_t)MROWS * DIM / 4);
    half_pass<<<112, 256>>>(qkv_w, w1h, (size_t)N1 * KDIM / 4);
    half_pass<<<48, 256>>>(proj_w, w2h, (size_t)DIM * KDIM / 4);
    comb_pre<<<1536, 256>>>(bt, rel, mask, combp);

    dim3 g1(N1 / 128, MROWS / 128);    // 9 x 1568
    gemm_f16<<<g1, 256, SMEMH>>>(xh, w1h, qkv_b, nullptr, qp, kp, vp, 0);

    dim3 ga(NHEAD, BWIN);              // 12 x 4096
    attn_mma<<<ga, 128>>>(qp, kp, vp, combp, atth);

    dim3 g2(DIM / 128, MROWS / 128);   // 3 x 1568
    gemm_f16<<<g2, 256, SMEMH>>>(atth, w2h, proj_b, out, nullptr, nullptr, nullptr, 1);
}